// round 7
// baseline (speedup 1.0000x reference)
#include <cuda_runtime.h>
#include <cuda_bf16.h>
#include <cstdint>

// ---------------------------------------------------------------------------
// B=256, T=512, I=64, H=256, 2-layer bidirectional LSTM, FC on last timestep.
// R7: fixes R6's broken GEMM W-staging map (w_n covered only half the rows,
//     w_kq chunks overlapped/overflowed). Rest identical to R6:
//     producer-side bf16 hi/lo packing of h, acquire/release group barrier,
//     cp.async double-buffered tf32 GEMM with pre-rounded inputs.
// ---------------------------------------------------------------------------

__device__ float    g_xT  [512 * 64 * 256];
__device__ float    g_xp0f[512 * 1024 * 256];
__device__ float    g_xp0r[512 * 1024 * 256];
__device__ float    g_h0c [512 * 512 * 256];
__device__ float    g_xp1f[512 * 1024 * 256];
__device__ float    g_xp1r[1024 * 256];
__device__ float    g_h1  [512 * 256 * 256];
__device__ uint32_t g_hhi [512 * 2 * 128 * 256];   // h packed bf16x2 hi [t*NDIR+dir][kp][b]
__device__ uint32_t g_hlo [512 * 2 * 128 * 256];   // h packed bf16x2 lo
__device__ float    g_wt  [1024 * (64 + 64 + 512 + 512)];  // tf32-rounded W_ih's

__device__ unsigned g_gcnt[32 * 32];
__device__ unsigned g_ggen[32 * 32];

__device__ __forceinline__ float sigm(float x) { return 1.0f / (1.0f + __expf(-x)); }

__device__ __forceinline__ uint32_t f2tf32(float x) {
    uint32_t r;
    asm("cvt.rna.tf32.f32 %0, %1;" : "=r"(r) : "f"(x));
    return r;
}

__device__ __forceinline__ void mma_tf32(float c[4], const uint32_t a[4], const uint32_t b[2]) {
    asm volatile(
        "mma.sync.aligned.m16n8k8.row.col.f32.tf32.tf32.f32 "
        "{%0,%1,%2,%3}, {%4,%5,%6,%7}, {%8,%9}, {%0,%1,%2,%3};"
        : "+f"(c[0]), "+f"(c[1]), "+f"(c[2]), "+f"(c[3])
        : "r"(a[0]), "r"(a[1]), "r"(a[2]), "r"(a[3]), "r"(b[0]), "r"(b[1]));
}

__device__ __forceinline__ void mma_bf16(float c[4], const uint32_t a[4], const uint32_t b[2]) {
    asm volatile(
        "mma.sync.aligned.m16n8k16.row.col.f32.bf16.bf16.f32 "
        "{%0,%1,%2,%3}, {%4,%5,%6,%7}, {%8,%9}, {%0,%1,%2,%3};"
        : "+f"(c[0]), "+f"(c[1]), "+f"(c[2]), "+f"(c[3])
        : "r"(a[0]), "r"(a[1]), "r"(a[2]), "r"(a[3]), "r"(b[0]), "r"(b[1]));
}

__device__ __forceinline__ uint32_t packbf2(float a, float b) {
    __nv_bfloat162 t = __floats2bfloat162_rn(a, b);
    return *(uint32_t*)&t;
}

__device__ __forceinline__ void cp_async16(void* smem_dst, const void* gptr) {
    uint32_t sa = (uint32_t)__cvta_generic_to_shared(smem_dst);
    asm volatile("cp.async.cg.shared.global [%0], [%1], 16;" :: "r"(sa), "l"(gptr));
}
__device__ __forceinline__ void cp_commit() { asm volatile("cp.async.commit_group;"); }
template <int N>
__device__ __forceinline__ void cp_wait() { asm volatile("cp.async.wait_group %0;" :: "n"(N)); }

// Acquire/release group barrier: no MEMBAR, no sleep.
__device__ __forceinline__ void group_barrier(int grp, unsigned members) {
    __syncthreads();
    if (threadIdx.x == 0) {
        unsigned* cnt = &g_gcnt[grp * 32];
        unsigned* gen = &g_ggen[grp * 32];
        unsigned g0;
        asm volatile("ld.acquire.gpu.u32 %0, [%1];" : "=r"(g0) : "l"(gen));
        unsigned old;
        asm volatile("atom.acq_rel.gpu.add.u32 %0, [%1], 1;" : "=r"(old) : "l"(cnt));
        if (old == members - 1) {
            asm volatile("st.relaxed.gpu.u32 [%0], %1;" :: "l"(cnt), "r"(0u));
            asm volatile("red.release.gpu.add.u32 [%0], %1;" :: "l"(gen), "r"(1u));
        } else {
            unsigned g1;
            do {
                asm volatile("ld.acquire.gpu.u32 %0, [%1];" : "=r"(g1) : "l"(gen));
            } while (g1 == g0);
        }
    }
    __syncthreads();
}

// ---------------------------------------------------------------------------
// Transpose + tf32-round: x[b][t*64+k] -> xT[(t*64+k)][b]
// ---------------------------------------------------------------------------
__global__ void transpose_x(const float* __restrict__ x, float* __restrict__ xT) {
    __shared__ float tile[32][33];
    int c0 = blockIdx.x * 32, r0 = blockIdx.y * 32;
    int tx = threadIdx.x, ty = threadIdx.y;
#pragma unroll
    for (int i = 0; i < 32; i += 8)
        tile[ty + i][tx] = x[(size_t)(r0 + ty + i) * 32768 + c0 + tx];
    __syncthreads();
#pragma unroll
    for (int i = 0; i < 32; i += 8)
        xT[(size_t)(c0 + ty + i) * 256 + r0 + tx] =
            __uint_as_float(f2tf32(tile[tx][ty + i]));
}

// tf32-round a buffer (for weight pre-conversion)
__global__ void cvt_tf32(const float* __restrict__ in, float* __restrict__ out, int n) {
    int i = blockIdx.x * 256 + threadIdx.x;
    if (i < n) out[i] = __uint_as_float(f2tf32(in[i]));
}

// ---------------------------------------------------------------------------
// TF32 GEMM v2: inputs pre-rounded to tf32 (raw bit reinterpret), cp.async
// double-buffered staging, 2 CTAs/SM. C[t][n][m] = W[n][k]*A[t][k][m] + bias.
// ---------------------------------------------------------------------------
#define WS_STRIDE 20
#define AS_STRIDE 132

__global__ void __launch_bounds__(256, 2)
gemm_tf32(const float* __restrict__ A, const float* __restrict__ W,
          const float* __restrict__ b1, const float* __restrict__ b2,
          float* __restrict__ C, int K, int N) {
    __shared__ uint32_t Ws[2][128 * WS_STRIDE];
    __shared__ uint32_t As[2][16 * AS_STRIDE];

    int t  = blockIdx.x;
    int m0 = blockIdx.y * 128, n0 = blockIdx.z * 128;
    const float* At = A + (size_t)t * K * 256 + m0;
    const float* Wt = W + (size_t)n0 * K;
    float* Ct = C + (size_t)t * N * 256;

    int tid = threadIdx.x;
    int warp = tid >> 5, lane = tid & 31;
    int wn = (warp >> 2) * 64;
    int wb = (warp & 3) * 32;
    int lr = lane >> 2, lc = lane & 3;

    // staging indices
    int a_kk = tid >> 5,  a_b4 = (tid & 31) * 4;   // A: rows a_kk, a_kk+8
    int w_n  = tid >> 1,  w_k8 = (tid & 1) * 8;    // W: row w_n, 8 floats at w_k8

    float acc[4][4][4];
#pragma unroll
    for (int i = 0; i < 4; i++)
#pragma unroll
        for (int jj = 0; jj < 4; jj++)
#pragma unroll
            for (int r = 0; r < 4; r++) acc[i][jj][r] = 0.0f;

    auto stage = [&](int buf, int k0) {
        cp_async16(&As[buf][a_kk * AS_STRIDE + a_b4],
                   &At[(size_t)(k0 + a_kk) * 256 + a_b4]);
        cp_async16(&As[buf][(a_kk + 8) * AS_STRIDE + a_b4],
                   &At[(size_t)(k0 + a_kk + 8) * 256 + a_b4]);
        cp_async16(&Ws[buf][w_n * WS_STRIDE + w_k8],
                   &Wt[(size_t)w_n * K + k0 + w_k8]);
        cp_async16(&Ws[buf][w_n * WS_STRIDE + w_k8 + 4],
                   &Wt[(size_t)w_n * K + k0 + w_k8 + 4]);
    };

    int niter = K / 16;
    stage(0, 0);
    cp_commit();

    for (int it = 0; it < niter; it++) {
        int buf = it & 1;
        if (it + 1 < niter) {
            stage(buf ^ 1, (it + 1) * 16);
            cp_commit();
            cp_wait<1>();
        } else {
            cp_wait<0>();
        }
        __syncthreads();

#pragma unroll
        for (int ks = 0; ks < 2; ks++) {
            int kk = ks * 8;
            uint32_t a[4][4], b[4][2];
#pragma unroll
            for (int ni = 0; ni < 4; ni++) {
                int n = wn + ni * 16 + lr;
                a[ni][0] = Ws[buf][n * WS_STRIDE + kk + lc];
                a[ni][1] = Ws[buf][(n + 8) * WS_STRIDE + kk + lc];
                a[ni][2] = Ws[buf][n * WS_STRIDE + kk + lc + 4];
                a[ni][3] = Ws[buf][(n + 8) * WS_STRIDE + kk + lc + 4];
            }
#pragma unroll
            for (int bi = 0; bi < 4; bi++) {
                int bb = wb + bi * 8 + lr;
                b[bi][0] = As[buf][(kk + lc) * AS_STRIDE + bb];
                b[bi][1] = As[buf][(kk + lc + 4) * AS_STRIDE + bb];
            }
#pragma unroll
            for (int ni = 0; ni < 4; ni++)
#pragma unroll
                for (int bi = 0; bi < 4; bi++)
                    mma_tf32(acc[ni][bi], a[ni], b[bi]);
        }
        __syncthreads();
    }

#pragma unroll
    for (int ni = 0; ni < 4; ni++) {
#pragma unroll
        for (int h = 0; h < 2; h++) {
            int n = n0 + wn + ni * 16 + lr + h * 8;
            float bias = b1[n] + b2[n];
#pragma unroll
            for (int bi = 0; bi < 4; bi++) {
                int bb = m0 + wb + bi * 8 + lc * 2;
                float2 v = make_float2(acc[ni][bi][h * 2] + bias,
                                       acc[ni][bi][h * 2 + 1] + bias);
                *(float2*)&Ct[(size_t)n * 256 + bb] = v;
            }
        }
    }
}

// ---------------------------------------------------------------------------
// bf16 tensor-core persistent recurrence, 512 threads/CTA.
// h written as packed bf16x2 hi/lo (consumer raw-copies) + f32 for the GEMM
// (tf32-rounded when NDIR==2 since h0c only feeds GEMMs).
// ---------------------------------------------------------------------------
#define WS2 132
#define HS2 72
#define RGS 72

template <int NDIR>
__global__ void __launch_bounds__(512, 1)
lstm_rec_mma(const float* __restrict__ xp_f, const float* __restrict__ xp_r,
             const float* __restrict__ whh_f, const float* __restrict__ whh_r,
             float* __restrict__ hout,
             uint32_t* __restrict__ hhi, uint32_t* __restrict__ hlo) {
    constexpr int NG = 16, BGN = 4;
    constexpr int HOUT_ROWS = NDIR * 256;

    extern __shared__ char smraw[];
    uint32_t* W2hi = (uint32_t*)smraw;                 // [64][132]
    uint32_t* W2lo = W2hi + 64 * WS2;
    uint32_t* H2hi = W2lo + 64 * WS2;                  // [128][72]
    uint32_t* H2lo = H2hi + 128 * HS2;
    float*    gsh  = (float*)(H2lo + 128 * HS2);       // [64][72]

    int tid = threadIdx.x;
    int bx  = blockIdx.x;
    int dir = (NDIR == 2) ? (bx / (NG * BGN)) : 0;
    int rem = bx % (NG * BGN);
    int ng = rem / BGN, bg = rem % BGN;
    int u0 = ng * 16, b0 = bg * 64;
    int grp = dir * BGN + bg;

    const float* xp  = dir ? xp_r : xp_f;
    const float* whh = dir ? whh_r : whh_f;

    // stage W_hh slice once (hi/lo bf16x2, k-packed)
    for (int i = tid; i < 64 * 128; i += 512) {
        int r = i >> 7, kp = i & 127;
        int grow = (r >> 4) * 256 + u0 + (r & 15);
        float2 w = *(const float2*)&whh[(size_t)grow * 256 + 2 * kp];
        uint32_t hi = packbf2(w.x, w.y);
        __nv_bfloat162 hb = *(__nv_bfloat162*)&hi;
        W2hi[r * WS2 + kp] = hi;
        W2lo[r * WS2 + kp] = packbf2(w.x - __low2float(hb), w.y - __high2float(hb));
    }

    int warp = tid >> 5, lane = tid & 31;
    int rbase = (warp & 3) * 16;
    int bbase = (warp >> 2) * 16;
    int lr = lane >> 2, lc = lane & 3;

    // update mapping: unit pair j (0..7), batch ub (0..63)
    int j  = tid >> 6;
    int ub = tid & 63;
    float cr0 = 0.f, cr1 = 0.f;

    __syncthreads();

    for (int s = 0; s < 512; s++) {
        int t = dir ? (511 - s) : s;

        // prefetch xp gates for (units u0+2j, u0+2j+1, batch b0+ub)
        const float* xpt = xp + (size_t)t * 1024 * 256;
        float xg[4][2];
#pragma unroll
        for (int g = 0; g < 4; g++) {
            xg[g][0] = xpt[(size_t)(g * 256 + u0 + 2 * j) * 256 + b0 + ub];
            xg[g][1] = xpt[(size_t)(g * 256 + u0 + 2 * j + 1) * 256 + b0 + ub];
        }

        float acc[2][4];
#pragma unroll
        for (int bi = 0; bi < 2; bi++)
#pragma unroll
            for (int r = 0; r < 4; r++) acc[bi][r] = 0.0f;

        if (s > 0) {
            int tp = dir ? (t + 1) : (t - 1);
            size_t hbase = ((size_t)tp * NDIR + dir) * (128 * 256);
            // pure copy staging: LDG.128 -> STS.128
#pragma unroll
            for (int q = 0; q < 4; q++) {
                int i = tid + 512 * q;
                int kp = i >> 4, qq = (i & 15) * 4;
                *(uint4*)&H2hi[kp * HS2 + qq] =
                    *(const uint4*)&hhi[hbase + (size_t)kp * 256 + b0 + qq];
                *(uint4*)&H2lo[kp * HS2 + qq] =
                    *(const uint4*)&hlo[hbase + (size_t)kp * 256 + b0 + qq];
            }
            __syncthreads();

#pragma unroll 4
            for (int ch = 0; ch < 16; ch++) {
                int kk2 = ch * 8;
                uint32_t ahi[4], alo[4];
                int ra = (rbase + lr) * WS2 + kk2 + lc;
                ahi[0] = W2hi[ra];            ahi[2] = W2hi[ra + 4];
                ahi[1] = W2hi[ra + 8 * WS2];  ahi[3] = W2hi[ra + 8 * WS2 + 4];
                alo[0] = W2lo[ra];            alo[2] = W2lo[ra + 4];
                alo[1] = W2lo[ra + 8 * WS2];  alo[3] = W2lo[ra + 8 * WS2 + 4];
#pragma unroll
                for (int bi = 0; bi < 2; bi++) {
                    int bcol = bbase + bi * 8 + lr;
                    uint32_t bhi[2], blo[2];
                    bhi[0] = H2hi[(kk2 + lc) * HS2 + bcol];
                    bhi[1] = H2hi[(kk2 + lc + 4) * HS2 + bcol];
                    blo[0] = H2lo[(kk2 + lc) * HS2 + bcol];
                    blo[1] = H2lo[(kk2 + lc + 4) * HS2 + bcol];
                    mma_bf16(acc[bi], ahi, bhi);
                    mma_bf16(acc[bi], ahi, blo);
                    mma_bf16(acc[bi], alo, bhi);
                }
            }
        }

        // gates -> gsh
#pragma unroll
        for (int bi = 0; bi < 2; bi++) {
            int col = bbase + bi * 8 + lc * 2;
            *(float2*)&gsh[(rbase + lr) * RGS + col]     = make_float2(acc[bi][0], acc[bi][1]);
            *(float2*)&gsh[(rbase + lr + 8) * RGS + col] = make_float2(acc[bi][2], acc[bi][3]);
        }
        __syncthreads();

        // LSTM update: units 2j, 2j+1 at batch ub
        float gv[4][2];
#pragma unroll
        for (int g = 0; g < 4; g++) {
            gv[g][0] = xg[g][0] + gsh[(g * 16 + 2 * j) * RGS + ub];
            gv[g][1] = xg[g][1] + gsh[(g * 16 + 2 * j + 1) * RGS + ub];
        }
        cr0 = sigm(gv[1][0]) * cr0 + sigm(gv[0][0]) * tanhf(gv[2][0]);
        cr1 = sigm(gv[1][1]) * cr1 + sigm(gv[0][1]) * tanhf(gv[2][1]);
        float h0 = sigm(gv[3][0]) * tanhf(cr0);
        float h1 = sigm(gv[3][1]) * tanhf(cr1);

        // packed hi/lo store for next-step consumers
        uint32_t hiw = packbf2(h0, h1);
        __nv_bfloat162 hb = *(__nv_bfloat162*)&hiw;
        uint32_t low = packbf2(h0 - __low2float(hb), h1 - __high2float(hb));
        size_t kidx = ((size_t)t * NDIR + dir) * (128 * 256) +
                      (size_t)(u0 / 2 + j) * 256 + b0 + ub;
        hhi[kidx] = hiw;
        hlo[kidx] = low;

        // f32 store (tf32-rounded for L0: h0c feeds GEMMs only)
        float o0 = (NDIR == 2) ? __uint_as_float(f2tf32(h0)) : h0;
        float o1 = (NDIR == 2) ? __uint_as_float(f2tf32(h1)) : h1;
        size_t orow = (size_t)t * HOUT_ROWS + dir * 256 + u0 + 2 * j;
        hout[orow * 256 + b0 + ub]       = o0;
        hout[(orow + 1) * 256 + b0 + ub] = o1;

        group_barrier(grp, NG);
    }
}

// ---------------------------------------------------------------------------
__global__ void finalize_kernel(const float* __restrict__ xp1r,
                                const float* __restrict__ h1last,
                                const float* __restrict__ fc_w,
                                const float* __restrict__ fc_b,
                                float* __restrict__ out) {
    int b = blockIdx.x, u = threadIdx.x;
    float ig = xp1r[(size_t)(0   + u) * 256 + b];
    float gg = xp1r[(size_t)(512 + u) * 256 + b];
    float og = xp1r[(size_t)(768 + u) * 256 + b];
    float cc = sigm(ig) * tanhf(gg);
    float hr = sigm(og) * tanhf(cc);
    float p = fc_w[u] * h1last[(size_t)u * 256 + b] + fc_w[256 + u] * hr;
    __shared__ float red[256];
    red[u] = p;
    __syncthreads();
    for (int off = 128; off > 0; off >>= 1) {
        if (u < off) red[u] += red[u + off];
        __syncthreads();
    }
    if (u == 0) out[b] = red[0] + fc_b[0];
}

// ---------------------------------------------------------------------------
extern "C" void kernel_launch(void* const* d_in, const int* in_sizes, int n_in,
                              void* d_out, int out_size) {
    const float* x        = (const float*)d_in[0];
    const float* w_ih_l0  = (const float*)d_in[1];
    const float* w_hh_l0  = (const float*)d_in[2];
    const float* b_ih_l0  = (const float*)d_in[3];
    const float* b_hh_l0  = (const float*)d_in[4];
    const float* w_ih_l0r = (const float*)d_in[5];
    const float* w_hh_l0r = (const float*)d_in[6];
    const float* b_ih_l0r = (const float*)d_in[7];
    const float* b_hh_l0r = (const float*)d_in[8];
    const float* w_ih_l1  = (const float*)d_in[9];
    const float* w_hh_l1  = (const float*)d_in[10];
    const float* b_ih_l1  = (const float*)d_in[11];
    const float* b_hh_l1  = (const float*)d_in[12];
    const float* w_ih_l1r = (const float*)d_in[13];
    const float* b_ih_l1r = (const float*)d_in[15];
    const float* b_hh_l1r = (const float*)d_in[16];
    const float* fc_w     = (const float*)d_in[17];
    const float* fc_b     = (const float*)d_in[18];
    float* out = (float*)d_out;
    (void)in_sizes; (void)n_in; (void)out_size;

    float *xT, *xp0f, *xp0r, *h0c, *xp1f, *xp1r, *h1, *wt;
    uint32_t *hhi, *hlo;
    cudaGetSymbolAddress((void**)&xT,   g_xT);
    cudaGetSymbolAddress((void**)&xp0f, g_xp0f);
    cudaGetSymbolAddress((void**)&xp0r, g_xp0r);
    cudaGetSymbolAddress((void**)&h0c,  g_h0c);
    cudaGetSymbolAddress((void**)&xp1f, g_xp1f);
    cudaGetSymbolAddress((void**)&xp1r, g_xp1r);
    cudaGetSymbolAddress((void**)&h1,   g_h1);
    cudaGetSymbolAddress((void**)&wt,   g_wt);
    cudaGetSymbolAddress((void**)&hhi,  g_hhi);
    cudaGetSymbolAddress((void**)&hlo,  g_hlo);

    float* wt_l0  = wt;
    float* wt_l0r = wt + 1024 * 64;
    float* wt_l1  = wt + 1024 * 128;
    float* wt_l1r = wt + 1024 * 128 + 1024 * 512;

    const int REC_SMEM = (64 * WS2 * 2 + 128 * HS2 * 2 + 64 * RGS) * 4;
    cudaFuncSetAttribute((const void*)lstm_rec_mma<2>,
                         cudaFuncAttributeMaxDynamicSharedMemorySize, REC_SMEM);
    cudaFuncSetAttribute((const void*)lstm_rec_mma<1>,
                         cudaFuncAttributeMaxDynamicSharedMemorySize, REC_SMEM);

    // weight pre-conversion (tiny)
    cvt_tf32<<<(1024 * 64  + 255) / 256, 256>>>(w_ih_l0,  wt_l0,  1024 * 64);
    cvt_tf32<<<(1024 * 64  + 255) / 256, 256>>>(w_ih_l0r, wt_l0r, 1024 * 64);
    cvt_tf32<<<(1024 * 512 + 255) / 256, 256>>>(w_ih_l1,  wt_l1,  1024 * 512);
    cvt_tf32<<<(1024 * 512 + 255) / 256, 256>>>(w_ih_l1r, wt_l1r, 1024 * 512);

    transpose_x<<<dim3(1024, 8), dim3(32, 8)>>>(x, xT);
    gemm_tf32<<<dim3(512, 2, 8), 256>>>(xT, wt_l0,  b_ih_l0,  b_hh_l0,  xp0f, 64, 1024);
    gemm_tf32<<<dim3(512, 2, 8), 256>>>(xT, wt_l0r, b_ih_l0r, b_hh_l0r, xp0r, 64, 1024);
    lstm_rec_mma<2><<<128, 512, REC_SMEM>>>(xp0f, xp0r, w_hh_l0, w_hh_l0r, h0c, hhi, hlo);
    gemm_tf32<<<dim3(512, 2, 8), 256>>>(h0c, wt_l1, b_ih_l1, b_hh_l1, xp1f, 512, 1024);
    gemm_tf32<<<dim3(1, 2, 8), 256>>>(h0c + (size_t)511 * 512 * 256,
                                      wt_l1r, b_ih_l1r, b_hh_l1r, xp1r, 512, 1024);
    lstm_rec_mma<1><<<64, 512, REC_SMEM>>>(xp1f, xp1f, w_hh_l1, w_hh_l1, h1, hhi, hlo);
    finalize_kernel<<<256, 256>>>(xp1r, h1 + (size_t)511 * 256 * 256, fc_w, fc_b, out);
}

// round 8
// speedup vs baseline: 1.4529x; 1.4529x over previous
#include <cuda_runtime.h>
#include <cuda_bf16.h>
#include <cstdint>

// ---------------------------------------------------------------------------
// B=256, T=512, I=64, H=256, 2-layer bidirectional LSTM, FC on last timestep.
// R8: GEMM reverted to proven R5 version (R7's launch_bounds(256,2) caused
//     register spills in the dominant GEMM). Keeps R7 recurrence improvements:
//     producer-side bf16 hi/lo packed h exchange + acquire/release barrier.
//     L1 recurrence skips f32 h stores except t=511 (only FC reads it).
// ---------------------------------------------------------------------------

__device__ float    g_xT  [512 * 64 * 256];
__device__ float    g_xp0f[512 * 1024 * 256];
__device__ float    g_xp0r[512 * 1024 * 256];
__device__ float    g_h0c [512 * 512 * 256];
__device__ float    g_xp1f[512 * 1024 * 256];
__device__ float    g_xp1r[1024 * 256];
__device__ float    g_h1  [512 * 256 * 256];
__device__ uint32_t g_hhi [512 * 2 * 128 * 256];   // h packed bf16x2 hi [t*NDIR+dir][kp][b]
__device__ uint32_t g_hlo [512 * 2 * 128 * 256];   // h packed bf16x2 lo

__device__ unsigned g_gcnt[32 * 32];
__device__ unsigned g_ggen[32 * 32];

__device__ __forceinline__ float sigm(float x) { return 1.0f / (1.0f + __expf(-x)); }

__device__ __forceinline__ uint32_t f2tf32(float x) {
    uint32_t r;
    asm("cvt.rna.tf32.f32 %0, %1;" : "=r"(r) : "f"(x));
    return r;
}

__device__ __forceinline__ void mma_tf32(float c[4], const uint32_t a[4], const uint32_t b[2]) {
    asm volatile(
        "mma.sync.aligned.m16n8k8.row.col.f32.tf32.tf32.f32 "
        "{%0,%1,%2,%3}, {%4,%5,%6,%7}, {%8,%9}, {%0,%1,%2,%3};"
        : "+f"(c[0]), "+f"(c[1]), "+f"(c[2]), "+f"(c[3])
        : "r"(a[0]), "r"(a[1]), "r"(a[2]), "r"(a[3]), "r"(b[0]), "r"(b[1]));
}

__device__ __forceinline__ void mma_bf16(float c[4], const uint32_t a[4], const uint32_t b[2]) {
    asm volatile(
        "mma.sync.aligned.m16n8k16.row.col.f32.bf16.bf16.f32 "
        "{%0,%1,%2,%3}, {%4,%5,%6,%7}, {%8,%9}, {%0,%1,%2,%3};"
        : "+f"(c[0]), "+f"(c[1]), "+f"(c[2]), "+f"(c[3])
        : "r"(a[0]), "r"(a[1]), "r"(a[2]), "r"(a[3]), "r"(b[0]), "r"(b[1]));
}

__device__ __forceinline__ uint32_t packbf2(float a, float b) {
    __nv_bfloat162 t = __floats2bfloat162_rn(a, b);
    return *(uint32_t*)&t;
}

// Acquire/release group barrier: no MEMBAR, no sleep.
__device__ __forceinline__ void group_barrier(int grp, unsigned members) {
    __syncthreads();
    if (threadIdx.x == 0) {
        unsigned* cnt = &g_gcnt[grp * 32];
        unsigned* gen = &g_ggen[grp * 32];
        unsigned g0;
        asm volatile("ld.acquire.gpu.u32 %0, [%1];" : "=r"(g0) : "l"(gen));
        unsigned old;
        asm volatile("atom.acq_rel.gpu.add.u32 %0, [%1], 1;" : "=r"(old) : "l"(cnt));
        if (old == members - 1) {
            asm volatile("st.relaxed.gpu.u32 [%0], %1;" :: "l"(cnt), "r"(0u));
            asm volatile("red.release.gpu.add.u32 [%0], %1;" :: "l"(gen), "r"(1u));
        } else {
            unsigned g1;
            do {
                asm volatile("ld.acquire.gpu.u32 %0, [%1];" : "=r"(g1) : "l"(gen));
            } while (g1 == g0);
        }
    }
    __syncthreads();
}

// ---------------------------------------------------------------------------
// Transpose x[b][t*64+k] -> xT[(t*64+k)][b]
// ---------------------------------------------------------------------------
__global__ void transpose_x(const float* __restrict__ x, float* __restrict__ xT) {
    __shared__ float tile[32][33];
    int c0 = blockIdx.x * 32, r0 = blockIdx.y * 32;
    int tx = threadIdx.x, ty = threadIdx.y;
#pragma unroll
    for (int i = 0; i < 32; i += 8)
        tile[ty + i][tx] = x[(size_t)(r0 + ty + i) * 32768 + c0 + tx];
    __syncthreads();
#pragma unroll
    for (int i = 0; i < 32; i += 8)
        xT[(size_t)(c0 + ty + i) * 256 + r0 + tx] = tile[tx][ty + i];
}

// ---------------------------------------------------------------------------
// TF32 tensor-core GEMM (proven R5 version: staging-time convert, single buf).
// C[t][n][m] = sum_k W[n][k]*A[t][k][m] + b1[n] + b2[n]
// ---------------------------------------------------------------------------
#define WS_STRIDE 20
#define AS_STRIDE 132

__global__ void gemm_tf32(const float* __restrict__ A, const float* __restrict__ W,
                          const float* __restrict__ b1, const float* __restrict__ b2,
                          float* __restrict__ C, int K, int N) {
    __shared__ uint32_t Ws[128 * WS_STRIDE];
    __shared__ uint32_t As[16 * AS_STRIDE];

    int t  = blockIdx.x;
    int m0 = blockIdx.y * 128, n0 = blockIdx.z * 128;
    const float* At = A + (size_t)t * K * 256 + m0;
    const float* Wt = W + (size_t)n0 * K;
    float* Ct = C + (size_t)t * N * 256;

    int tid = threadIdx.x;
    int warp = tid >> 5, lane = tid & 31;
    int wn = (warp >> 2) * 64;
    int wb = (warp & 3) * 32;
    int lr = lane >> 2, lc = lane & 3;

    float acc[4][4][4];
#pragma unroll
    for (int i = 0; i < 4; i++)
#pragma unroll
        for (int jj = 0; jj < 4; jj++)
#pragma unroll
            for (int r = 0; r < 4; r++) acc[i][jj][r] = 0.0f;

    for (int k0 = 0; k0 < K; k0 += 16) {
#pragma unroll
        for (int q = 0; q < 2; q++) {
            int f = tid + 256 * q;
            int kk = f >> 5, b4 = (f & 31) * 4;
            float4 v = *(const float4*)&At[(size_t)(k0 + kk) * 256 + b4];
            uint4 u = make_uint4(f2tf32(v.x), f2tf32(v.y), f2tf32(v.z), f2tf32(v.w));
            *(uint4*)&As[kk * AS_STRIDE + b4] = u;
        }
#pragma unroll
        for (int q = 0; q < 2; q++) {
            int f = tid + 256 * q;
            int n = f >> 2, kq = (f & 3) * 4;
            float4 v = *(const float4*)&Wt[(size_t)n * K + k0 + kq];
            uint4 u = make_uint4(f2tf32(v.x), f2tf32(v.y), f2tf32(v.z), f2tf32(v.w));
            *(uint4*)&Ws[n * WS_STRIDE + kq] = u;
        }
        __syncthreads();

#pragma unroll
        for (int ks = 0; ks < 2; ks++) {
            int kk = ks * 8;
            uint32_t a[4][4], b[4][2];
#pragma unroll
            for (int ni = 0; ni < 4; ni++) {
                int n = wn + ni * 16 + lr;
                a[ni][0] = Ws[n * WS_STRIDE + kk + lc];
                a[ni][1] = Ws[(n + 8) * WS_STRIDE + kk + lc];
                a[ni][2] = Ws[n * WS_STRIDE + kk + lc + 4];
                a[ni][3] = Ws[(n + 8) * WS_STRIDE + kk + lc + 4];
            }
#pragma unroll
            for (int bi = 0; bi < 4; bi++) {
                int bb = wb + bi * 8 + lr;
                b[bi][0] = As[(kk + lc) * AS_STRIDE + bb];
                b[bi][1] = As[(kk + lc + 4) * AS_STRIDE + bb];
            }
#pragma unroll
            for (int ni = 0; ni < 4; ni++)
#pragma unroll
                for (int bi = 0; bi < 4; bi++)
                    mma_tf32(acc[ni][bi], a[ni], b[bi]);
        }
        __syncthreads();
    }

#pragma unroll
    for (int ni = 0; ni < 4; ni++) {
#pragma unroll
        for (int h = 0; h < 2; h++) {
            int n = n0 + wn + ni * 16 + lr + h * 8;
            float bias = b1[n] + b2[n];
#pragma unroll
            for (int bi = 0; bi < 4; bi++) {
                int bb = m0 + wb + bi * 8 + lc * 2;
                float2 v = make_float2(acc[ni][bi][h * 2] + bias,
                                       acc[ni][bi][h * 2 + 1] + bias);
                *(float2*)&Ct[(size_t)n * 256 + bb] = v;
            }
        }
    }
}

// ---------------------------------------------------------------------------
// bf16 tensor-core persistent recurrence, 512 threads/CTA.
// h exchanged as packed bf16x2 hi/lo (producer packs, consumer raw-copies).
// f32 h stored for GEMM consumers (L0 always; L1 only at t=511 for FC head).
// ---------------------------------------------------------------------------
#define WS2 132
#define HS2 72
#define RGS 72

template <int NDIR>
__global__ void __launch_bounds__(512, 1)
lstm_rec_mma(const float* __restrict__ xp_f, const float* __restrict__ xp_r,
             const float* __restrict__ whh_f, const float* __restrict__ whh_r,
             float* __restrict__ hout,
             uint32_t* __restrict__ hhi, uint32_t* __restrict__ hlo) {
    constexpr int NG = 16, BGN = 4;
    constexpr int HOUT_ROWS = NDIR * 256;

    extern __shared__ char smraw[];
    uint32_t* W2hi = (uint32_t*)smraw;                 // [64][132]
    uint32_t* W2lo = W2hi + 64 * WS2;
    uint32_t* H2hi = W2lo + 64 * WS2;                  // [128][72]
    uint32_t* H2lo = H2hi + 128 * HS2;
    float*    gsh  = (float*)(H2lo + 128 * HS2);       // [64][72]

    int tid = threadIdx.x;
    int bx  = blockIdx.x;
    int dir = (NDIR == 2) ? (bx / (NG * BGN)) : 0;
    int rem = bx % (NG * BGN);
    int ng = rem / BGN, bg = rem % BGN;
    int u0 = ng * 16, b0 = bg * 64;
    int grp = dir * BGN + bg;

    const float* xp  = dir ? xp_r : xp_f;
    const float* whh = dir ? whh_r : whh_f;

    // stage W_hh slice once (hi/lo bf16x2, k-packed)
    for (int i = tid; i < 64 * 128; i += 512) {
        int r = i >> 7, kp = i & 127;
        int grow = (r >> 4) * 256 + u0 + (r & 15);
        float2 w = *(const float2*)&whh[(size_t)grow * 256 + 2 * kp];
        uint32_t hi = packbf2(w.x, w.y);
        __nv_bfloat162 hb = *(__nv_bfloat162*)&hi;
        W2hi[r * WS2 + kp] = hi;
        W2lo[r * WS2 + kp] = packbf2(w.x - __low2float(hb), w.y - __high2float(hb));
    }

    int warp = tid >> 5, lane = tid & 31;
    int rbase = (warp & 3) * 16;
    int bbase = (warp >> 2) * 16;
    int lr = lane >> 2, lc = lane & 3;

    // update mapping: unit pair j (0..7), batch ub (0..63)
    int j  = tid >> 6;
    int ub = tid & 63;
    float cr0 = 0.f, cr1 = 0.f;

    __syncthreads();

    for (int s = 0; s < 512; s++) {
        int t = dir ? (511 - s) : s;

        // prefetch xp gates for (units u0+2j, u0+2j+1, batch b0+ub)
        const float* xpt = xp + (size_t)t * 1024 * 256;
        float xg[4][2];
#pragma unroll
        for (int g = 0; g < 4; g++) {
            xg[g][0] = xpt[(size_t)(g * 256 + u0 + 2 * j) * 256 + b0 + ub];
            xg[g][1] = xpt[(size_t)(g * 256 + u0 + 2 * j + 1) * 256 + b0 + ub];
        }

        float acc[2][4];
#pragma unroll
        for (int bi = 0; bi < 2; bi++)
#pragma unroll
            for (int r = 0; r < 4; r++) acc[bi][r] = 0.0f;

        if (s > 0) {
            int tp = dir ? (t + 1) : (t - 1);
            size_t hbase = ((size_t)tp * NDIR + dir) * (128 * 256);
            // pure copy staging: LDG.128 -> STS.128
#pragma unroll
            for (int q = 0; q < 4; q++) {
                int i = tid + 512 * q;
                int kp = i >> 4, qq = (i & 15) * 4;
                *(uint4*)&H2hi[kp * HS2 + qq] =
                    *(const uint4*)&hhi[hbase + (size_t)kp * 256 + b0 + qq];
                *(uint4*)&H2lo[kp * HS2 + qq] =
                    *(const uint4*)&hlo[hbase + (size_t)kp * 256 + b0 + qq];
            }
            __syncthreads();

#pragma unroll 4
            for (int ch = 0; ch < 16; ch++) {
                int kk2 = ch * 8;
                uint32_t ahi[4], alo[4];
                int ra = (rbase + lr) * WS2 + kk2 + lc;
                ahi[0] = W2hi[ra];            ahi[2] = W2hi[ra + 4];
                ahi[1] = W2hi[ra + 8 * WS2];  ahi[3] = W2hi[ra + 8 * WS2 + 4];
                alo[0] = W2lo[ra];            alo[2] = W2lo[ra + 4];
                alo[1] = W2lo[ra + 8 * WS2];  alo[3] = W2lo[ra + 8 * WS2 + 4];
#pragma unroll
                for (int bi = 0; bi < 2; bi++) {
                    int bcol = bbase + bi * 8 + lr;
                    uint32_t bhi[2], blo[2];
                    bhi[0] = H2hi[(kk2 + lc) * HS2 + bcol];
                    bhi[1] = H2hi[(kk2 + lc + 4) * HS2 + bcol];
                    blo[0] = H2lo[(kk2 + lc) * HS2 + bcol];
                    blo[1] = H2lo[(kk2 + lc + 4) * HS2 + bcol];
                    mma_bf16(acc[bi], ahi, bhi);
                    mma_bf16(acc[bi], ahi, blo);
                    mma_bf16(acc[bi], alo, bhi);
                }
            }
        }

        // gates -> gsh
#pragma unroll
        for (int bi = 0; bi < 2; bi++) {
            int col = bbase + bi * 8 + lc * 2;
            *(float2*)&gsh[(rbase + lr) * RGS + col]     = make_float2(acc[bi][0], acc[bi][1]);
            *(float2*)&gsh[(rbase + lr + 8) * RGS + col] = make_float2(acc[bi][2], acc[bi][3]);
        }
        __syncthreads();

        // LSTM update: units 2j, 2j+1 at batch ub
        float gv[4][2];
#pragma unroll
        for (int g = 0; g < 4; g++) {
            gv[g][0] = xg[g][0] + gsh[(g * 16 + 2 * j) * RGS + ub];
            gv[g][1] = xg[g][1] + gsh[(g * 16 + 2 * j + 1) * RGS + ub];
        }
        cr0 = sigm(gv[1][0]) * cr0 + sigm(gv[0][0]) * tanhf(gv[2][0]);
        cr1 = sigm(gv[1][1]) * cr1 + sigm(gv[0][1]) * tanhf(gv[2][1]);
        float h0 = sigm(gv[3][0]) * tanhf(cr0);
        float h1 = sigm(gv[3][1]) * tanhf(cr1);

        // packed hi/lo store for next-step consumers
        uint32_t hiw = packbf2(h0, h1);
        __nv_bfloat162 hb = *(__nv_bfloat162*)&hiw;
        uint32_t low = packbf2(h0 - __low2float(hb), h1 - __high2float(hb));
        size_t kidx = ((size_t)t * NDIR + dir) * (128 * 256) +
                      (size_t)(u0 / 2 + j) * 256 + b0 + ub;
        hhi[kidx] = hiw;
        hlo[kidx] = low;

        // f32 store: L0 always (h0c feeds GEMMs); L1 only t=511 (FC head)
        if (NDIR == 2 || t == 511) {
            size_t orow = (size_t)t * HOUT_ROWS + dir * 256 + u0 + 2 * j;
            hout[orow * 256 + b0 + ub]       = h0;
            hout[(orow + 1) * 256 + b0 + ub] = h1;
        }

        group_barrier(grp, NG);
    }
}

// ---------------------------------------------------------------------------
__global__ void finalize_kernel(const float* __restrict__ xp1r,
                                const float* __restrict__ h1last,
                                const float* __restrict__ fc_w,
                                const float* __restrict__ fc_b,
                                float* __restrict__ out) {
    int b = blockIdx.x, u = threadIdx.x;
    float ig = xp1r[(size_t)(0   + u) * 256 + b];
    float gg = xp1r[(size_t)(512 + u) * 256 + b];
    float og = xp1r[(size_t)(768 + u) * 256 + b];
    float cc = sigm(ig) * tanhf(gg);
    float hr = sigm(og) * tanhf(cc);
    float p = fc_w[u] * h1last[(size_t)u * 256 + b] + fc_w[256 + u] * hr;
    __shared__ float red[256];
    red[u] = p;
    __syncthreads();
    for (int off = 128; off > 0; off >>= 1) {
        if (u < off) red[u] += red[u + off];
        __syncthreads();
    }
    if (u == 0) out[b] = red[0] + fc_b[0];
}

// ---------------------------------------------------------------------------
extern "C" void kernel_launch(void* const* d_in, const int* in_sizes, int n_in,
                              void* d_out, int out_size) {
    const float* x        = (const float*)d_in[0];
    const float* w_ih_l0  = (const float*)d_in[1];
    const float* w_hh_l0  = (const float*)d_in[2];
    const float* b_ih_l0  = (const float*)d_in[3];
    const float* b_hh_l0  = (const float*)d_in[4];
    const float* w_ih_l0r = (const float*)d_in[5];
    const float* w_hh_l0r = (const float*)d_in[6];
    const float* b_ih_l0r = (const float*)d_in[7];
    const float* b_hh_l0r = (const float*)d_in[8];
    const float* w_ih_l1  = (const float*)d_in[9];
    const float* w_hh_l1  = (const float*)d_in[10];
    const float* b_ih_l1  = (const float*)d_in[11];
    const float* b_hh_l1  = (const float*)d_in[12];
    const float* w_ih_l1r = (const float*)d_in[13];
    const float* b_ih_l1r = (const float*)d_in[15];
    const float* b_hh_l1r = (const float*)d_in[16];
    const float* fc_w     = (const float*)d_in[17];
    const float* fc_b     = (const float*)d_in[18];
    float* out = (float*)d_out;
    (void)in_sizes; (void)n_in; (void)out_size;

    float *xT, *xp0f, *xp0r, *h0c, *xp1f, *xp1r, *h1;
    uint32_t *hhi, *hlo;
    cudaGetSymbolAddress((void**)&xT,   g_xT);
    cudaGetSymbolAddress((void**)&xp0f, g_xp0f);
    cudaGetSymbolAddress((void**)&xp0r, g_xp0r);
    cudaGetSymbolAddress((void**)&h0c,  g_h0c);
    cudaGetSymbolAddress((void**)&xp1f, g_xp1f);
    cudaGetSymbolAddress((void**)&xp1r, g_xp1r);
    cudaGetSymbolAddress((void**)&h1,   g_h1);
    cudaGetSymbolAddress((void**)&hhi,  g_hhi);
    cudaGetSymbolAddress((void**)&hlo,  g_hlo);

    const int REC_SMEM = (64 * WS2 * 2 + 128 * HS2 * 2 + 64 * RGS) * 4;
    cudaFuncSetAttribute((const void*)lstm_rec_mma<2>,
                         cudaFuncAttributeMaxDynamicSharedMemorySize, REC_SMEM);
    cudaFuncSetAttribute((const void*)lstm_rec_mma<1>,
                         cudaFuncAttributeMaxDynamicSharedMemorySize, REC_SMEM);

    transpose_x<<<dim3(1024, 8), dim3(32, 8)>>>(x, xT);
    gemm_tf32<<<dim3(512, 2, 8), 256>>>(xT, w_ih_l0,  b_ih_l0,  b_hh_l0,  xp0f, 64, 1024);
    gemm_tf32<<<dim3(512, 2, 8), 256>>>(xT, w_ih_l0r, b_ih_l0r, b_hh_l0r, xp0r, 64, 1024);
    lstm_rec_mma<2><<<128, 512, REC_SMEM>>>(xp0f, xp0r, w_hh_l0, w_hh_l0r, h0c, hhi, hlo);
    gemm_tf32<<<dim3(512, 2, 8), 256>>>(h0c, w_ih_l1, b_ih_l1, b_hh_l1, xp1f, 512, 1024);
    gemm_tf32<<<dim3(1, 2, 8), 256>>>(h0c + (size_t)511 * 512 * 256,
                                      w_ih_l1r, b_ih_l1r, b_hh_l1r, xp1r, 512, 1024);
    lstm_rec_mma<1><<<64, 512, REC_SMEM>>>(xp1f, xp1f, w_hh_l1, w_hh_l1, h1, hhi, hlo);
    finalize_kernel<<<256, 256>>>(xp1r, h1 + (size_t)511 * 256 * 256, fc_w, fc_b, out);
}

// round 10
// speedup vs baseline: 1.5359x; 1.0571x over previous
#include <cuda_runtime.h>
#include <cuda_bf16.h>
#include <cstdint>

// ---------------------------------------------------------------------------
// B=256, T=512, I=64, H=256, 2-layer bidirectional LSTM, FC on last timestep.
// R10: R9's re-tiled recurrence (32 units x 32 batches per CTA, 8-member
//      groups, halved h staging) + GEMM register-prefetch, but with the
//      PROVEN R8 acquire/release atomic group barrier (R9's flag sync
//      deadlocked: step-0 flag value collided with the zero-initialized flag).
// ---------------------------------------------------------------------------

__device__ float    g_xT  [512 * 64 * 256];
__device__ float    g_xp0f[512 * 1024 * 256];
__device__ float    g_xp0r[512 * 1024 * 256];
__device__ float    g_h0c [512 * 512 * 256];
__device__ float    g_xp1f[512 * 1024 * 256];
__device__ float    g_xp1r[1024 * 256];
__device__ float    g_h1  [512 * 256 * 256];
__device__ uint32_t g_hhi [512 * 2 * 128 * 256];   // h packed bf16x2 hi [t*NDIR+dir][kp][b]
__device__ uint32_t g_hlo [512 * 2 * 128 * 256];   // h packed bf16x2 lo

__device__ unsigned g_gcnt[32 * 32];
__device__ unsigned g_ggen[32 * 32];

__device__ __forceinline__ float sigm(float x) { return 1.0f / (1.0f + __expf(-x)); }

__device__ __forceinline__ uint32_t f2tf32(float x) {
    uint32_t r;
    asm("cvt.rna.tf32.f32 %0, %1;" : "=r"(r) : "f"(x));
    return r;
}

__device__ __forceinline__ void mma_tf32(float c[4], const uint32_t a[4], const uint32_t b[2]) {
    asm volatile(
        "mma.sync.aligned.m16n8k8.row.col.f32.tf32.tf32.f32 "
        "{%0,%1,%2,%3}, {%4,%5,%6,%7}, {%8,%9}, {%0,%1,%2,%3};"
        : "+f"(c[0]), "+f"(c[1]), "+f"(c[2]), "+f"(c[3])
        : "r"(a[0]), "r"(a[1]), "r"(a[2]), "r"(a[3]), "r"(b[0]), "r"(b[1]));
}

__device__ __forceinline__ void mma_bf16(float c[4], const uint32_t a[4], const uint32_t b[2]) {
    asm volatile(
        "mma.sync.aligned.m16n8k16.row.col.f32.bf16.bf16.f32 "
        "{%0,%1,%2,%3}, {%4,%5,%6,%7}, {%8,%9}, {%0,%1,%2,%3};"
        : "+f"(c[0]), "+f"(c[1]), "+f"(c[2]), "+f"(c[3])
        : "r"(a[0]), "r"(a[1]), "r"(a[2]), "r"(a[3]), "r"(b[0]), "r"(b[1]));
}

__device__ __forceinline__ uint32_t packbf2(float a, float b) {
    __nv_bfloat162 t = __floats2bfloat162_rn(a, b);
    return *(uint32_t*)&t;
}

// Proven acquire/release group barrier (R8): no MEMBAR, replay-safe.
__device__ __forceinline__ void group_barrier(int grp, unsigned members) {
    __syncthreads();
    if (threadIdx.x == 0) {
        unsigned* cnt = &g_gcnt[grp * 32];
        unsigned* gen = &g_ggen[grp * 32];
        unsigned g0;
        asm volatile("ld.acquire.gpu.u32 %0, [%1];" : "=r"(g0) : "l"(gen));
        unsigned old;
        asm volatile("atom.acq_rel.gpu.add.u32 %0, [%1], 1;" : "=r"(old) : "l"(cnt));
        if (old == members - 1) {
            asm volatile("st.relaxed.gpu.u32 [%0], %1;" :: "l"(cnt), "r"(0u));
            asm volatile("red.release.gpu.add.u32 [%0], %1;" :: "l"(gen), "r"(1u));
        } else {
            unsigned g1;
            do {
                asm volatile("ld.acquire.gpu.u32 %0, [%1];" : "=r"(g1) : "l"(gen));
            } while (g1 == g0);
        }
    }
    __syncthreads();
}

// ---------------------------------------------------------------------------
__global__ void transpose_x(const float* __restrict__ x, float* __restrict__ xT) {
    __shared__ float tile[32][33];
    int c0 = blockIdx.x * 32, r0 = blockIdx.y * 32;
    int tx = threadIdx.x, ty = threadIdx.y;
#pragma unroll
    for (int i = 0; i < 32; i += 8)
        tile[ty + i][tx] = x[(size_t)(r0 + ty + i) * 32768 + c0 + tx];
    __syncthreads();
#pragma unroll
    for (int i = 0; i < 32; i += 8)
        xT[(size_t)(c0 + ty + i) * 256 + r0 + tx] = tile[tx][ty + i];
}

// ---------------------------------------------------------------------------
// TF32 tensor-core GEMM with register-prefetch pipelining.
// C[t][n][m] = sum_k W[n][k]*A[t][k][m] + b1[n] + b2[n]
// ---------------------------------------------------------------------------
#define WS_STRIDE 20
#define AS_STRIDE 132

__global__ void gemm_tf32(const float* __restrict__ A, const float* __restrict__ W,
                          const float* __restrict__ b1, const float* __restrict__ b2,
                          float* __restrict__ C, int K, int N) {
    __shared__ uint32_t Ws[128 * WS_STRIDE];
    __shared__ uint32_t As[16 * AS_STRIDE];

    int t  = blockIdx.x;
    int m0 = blockIdx.y * 128, n0 = blockIdx.z * 128;
    const float* At = A + (size_t)t * K * 256 + m0;
    const float* Wt = W + (size_t)n0 * K;
    float* Ct = C + (size_t)t * N * 256;

    int tid = threadIdx.x;
    int warp = tid >> 5, lane = tid & 31;
    int wn = (warp >> 2) * 64;
    int wb = (warp & 3) * 32;
    int lr = lane >> 2, lc = lane & 3;

    int a_kk = tid >> 5, a_b4 = (tid & 31) * 4;
    int w_n  = tid >> 2, w_kq = (tid & 3) * 4;

    float acc[4][4][4];
#pragma unroll
    for (int i = 0; i < 4; i++)
#pragma unroll
        for (int jj = 0; jj < 4; jj++)
#pragma unroll
            for (int r = 0; r < 4; r++) acc[i][jj][r] = 0.0f;

    float4 ra0, ra1, rw0, rw1;
    auto ld = [&](int k0) {
        ra0 = *(const float4*)&At[(size_t)(k0 + a_kk) * 256 + a_b4];
        ra1 = *(const float4*)&At[(size_t)(k0 + a_kk + 8) * 256 + a_b4];
        rw0 = *(const float4*)&Wt[(size_t)w_n * K + k0 + w_kq];
        rw1 = *(const float4*)&Wt[(size_t)(w_n + 64) * K + k0 + w_kq];
    };
    auto st = [&]() {
        *(uint4*)&As[a_kk * AS_STRIDE + a_b4] =
            make_uint4(f2tf32(ra0.x), f2tf32(ra0.y), f2tf32(ra0.z), f2tf32(ra0.w));
        *(uint4*)&As[(a_kk + 8) * AS_STRIDE + a_b4] =
            make_uint4(f2tf32(ra1.x), f2tf32(ra1.y), f2tf32(ra1.z), f2tf32(ra1.w));
        *(uint4*)&Ws[w_n * WS_STRIDE + w_kq] =
            make_uint4(f2tf32(rw0.x), f2tf32(rw0.y), f2tf32(rw0.z), f2tf32(rw0.w));
        *(uint4*)&Ws[(w_n + 64) * WS_STRIDE + w_kq] =
            make_uint4(f2tf32(rw1.x), f2tf32(rw1.y), f2tf32(rw1.z), f2tf32(rw1.w));
    };

    int niter = K / 16;
    ld(0);
    for (int it = 0; it < niter; it++) {
        st();
        __syncthreads();
        if (it + 1 < niter) ld((it + 1) * 16);   // LDG overlaps MMA below

#pragma unroll
        for (int ks = 0; ks < 2; ks++) {
            int kk = ks * 8;
            uint32_t a[4][4], b[4][2];
#pragma unroll
            for (int ni = 0; ni < 4; ni++) {
                int n = wn + ni * 16 + lr;
                a[ni][0] = Ws[n * WS_STRIDE + kk + lc];
                a[ni][1] = Ws[(n + 8) * WS_STRIDE + kk + lc];
                a[ni][2] = Ws[n * WS_STRIDE + kk + lc + 4];
                a[ni][3] = Ws[(n + 8) * WS_STRIDE + kk + lc + 4];
            }
#pragma unroll
            for (int bi = 0; bi < 4; bi++) {
                int bb = wb + bi * 8 + lr;
                b[bi][0] = As[(kk + lc) * AS_STRIDE + bb];
                b[bi][1] = As[(kk + lc + 4) * AS_STRIDE + bb];
            }
#pragma unroll
            for (int ni = 0; ni < 4; ni++)
#pragma unroll
                for (int bi = 0; bi < 4; bi++)
                    mma_tf32(acc[ni][bi], a[ni], b[bi]);
        }
        __syncthreads();
    }

#pragma unroll
    for (int ni = 0; ni < 4; ni++) {
#pragma unroll
        for (int h = 0; h < 2; h++) {
            int n = n0 + wn + ni * 16 + lr + h * 8;
            float bias = b1[n] + b2[n];
#pragma unroll
            for (int bi = 0; bi < 4; bi++) {
                int bb = m0 + wb + bi * 8 + lc * 2;
                float2 v = make_float2(acc[ni][bi][h * 2] + bias,
                                       acc[ni][bi][h * 2 + 1] + bias);
                *(float2*)&Ct[(size_t)n * 256 + bb] = v;
            }
        }
    }
}

// ---------------------------------------------------------------------------
// bf16 tensor-core persistent recurrence, 512 threads/CTA.
// CTA = (dir, 32 units -> 128 gate rows, 32-batch slice). Groups of 8 CTAs
// share (dir, batch-slice); per-step sync via proven atomic group barrier.
// ---------------------------------------------------------------------------
#define WS2  132   // W2 row stride (128 kp + pad), mod32=4
#define HS2B 40    // H2 row stride (32 b + pad),  mod32=8
#define RGS2 36    // gsh row stride (32 b + pad)

template <int NDIR>
__global__ void __launch_bounds__(512, 1)
lstm_rec_mma(const float* __restrict__ xp_f, const float* __restrict__ xp_r,
             const float* __restrict__ whh_f, const float* __restrict__ whh_r,
             float* __restrict__ hout,
             uint32_t* __restrict__ hhi, uint32_t* __restrict__ hlo) {
    constexpr int NG = 8, BGN = 8;          // 8 CTAs per group, 8 batch slices
    constexpr int HOUT_ROWS = NDIR * 256;

    extern __shared__ char smraw[];
    uint32_t* W2hi = (uint32_t*)smraw;                 // [128][132]
    uint32_t* W2lo = W2hi + 128 * WS2;
    uint32_t* H2hi = W2lo + 128 * WS2;                 // [128][40]
    uint32_t* H2lo = H2hi + 128 * HS2B;
    float*    gsh  = (float*)(H2lo + 128 * HS2B);      // [128][36]

    int tid = threadIdx.x;
    int bx  = blockIdx.x;
    int dir = (NDIR == 2) ? (bx / (NG * BGN)) : 0;
    int rem = bx % (NG * BGN);
    int ng = rem / BGN, bg = rem % BGN;
    int u0 = ng * 32, b0 = bg * 32;
    int grp = dir * BGN + bg;

    const float* xp  = dir ? xp_r : xp_f;
    const float* whh = dir ? whh_r : whh_f;

    // stage W_hh slice once: local row r = gate*32 + unit, k packed in pairs
    for (int i = tid; i < 128 * 128; i += 512) {
        int r = i >> 7, kp = i & 127;
        int grow = (r >> 5) * 256 + u0 + (r & 31);
        float2 w = *(const float2*)&whh[(size_t)grow * 256 + 2 * kp];
        uint32_t hi = packbf2(w.x, w.y);
        __nv_bfloat162 hb = *(__nv_bfloat162*)&hi;
        W2hi[r * WS2 + kp] = hi;
        W2lo[r * WS2 + kp] = packbf2(w.x - __low2float(hb), w.y - __high2float(hb));
    }

    int warp = tid >> 5, lane = tid & 31;
    int rbase = (warp & 7) * 16;        // 8 gate-row tiles (128 rows)
    int bbase = (warp >> 3) * 16;       // 2 batch tiles (32 b)
    int lr = lane >> 2, lc = lane & 3;

    // update mapping: unit pair j (0..15), batch ub (0..31)
    int j  = tid >> 5;
    int ub = tid & 31;
    float cr0 = 0.f, cr1 = 0.f;

    __syncthreads();   // W staging complete (CTA-local)

    for (int s = 0; s < 512; s++) {
        int t = dir ? (511 - s) : s;

        // prefetch xp gates for (units u0+2j, u0+2j+1, batch b0+ub)
        const float* xpt = xp + (size_t)t * 1024 * 256;
        float xg[4][2];
#pragma unroll
        for (int g = 0; g < 4; g++) {
            xg[g][0] = xpt[(size_t)(g * 256 + u0 + 2 * j) * 256 + b0 + ub];
            xg[g][1] = xpt[(size_t)(g * 256 + u0 + 2 * j + 1) * 256 + b0 + ub];
        }

        float acc[2][4];
#pragma unroll
        for (int bi = 0; bi < 2; bi++)
#pragma unroll
            for (int r = 0; r < 4; r++) acc[bi][r] = 0.0f;

        if (s > 0) {
            int tp = dir ? (t + 1) : (t - 1);
            size_t hbase = ((size_t)tp * NDIR + dir) * (128 * 256);
            // stage h_prev (pure copy): 128 kp rows x 32 b words, hi+lo
#pragma unroll
            for (int q = 0; q < 2; q++) {
                int i = tid + 512 * q;
                int kp = i >> 3, qq = (i & 7) * 4;
                *(uint4*)&H2hi[kp * HS2B + qq] =
                    *(const uint4*)&hhi[hbase + (size_t)kp * 256 + b0 + qq];
                *(uint4*)&H2lo[kp * HS2B + qq] =
                    *(const uint4*)&hlo[hbase + (size_t)kp * 256 + b0 + qq];
            }
            __syncthreads();

#pragma unroll 4
            for (int ch = 0; ch < 16; ch++) {
                int kk2 = ch * 8;
                uint32_t ahi[4], alo[4];
                int ra = (rbase + lr) * WS2 + kk2 + lc;
                ahi[0] = W2hi[ra];            ahi[2] = W2hi[ra + 4];
                ahi[1] = W2hi[ra + 8 * WS2];  ahi[3] = W2hi[ra + 8 * WS2 + 4];
                alo[0] = W2lo[ra];            alo[2] = W2lo[ra + 4];
                alo[1] = W2lo[ra + 8 * WS2];  alo[3] = W2lo[ra + 8 * WS2 + 4];
#pragma unroll
                for (int bi = 0; bi < 2; bi++) {
                    int bcol = bbase + bi * 8 + lr;
                    uint32_t bhi[2], blo[2];
                    bhi[0] = H2hi[(kk2 + lc) * HS2B + bcol];
                    bhi[1] = H2hi[(kk2 + lc + 4) * HS2B + bcol];
                    blo[0] = H2lo[(kk2 + lc) * HS2B + bcol];
                    blo[1] = H2lo[(kk2 + lc + 4) * HS2B + bcol];
                    mma_bf16(acc[bi], ahi, bhi);
                    mma_bf16(acc[bi], ahi, blo);
                    mma_bf16(acc[bi], alo, bhi);
                }
            }
        }

        // gates -> gsh (each warp writes its own disjoint tile)
#pragma unroll
        for (int bi = 0; bi < 2; bi++) {
            int col = bbase + bi * 8 + lc * 2;
            *(float2*)&gsh[(rbase + lr) * RGS2 + col]     = make_float2(acc[bi][0], acc[bi][1]);
            *(float2*)&gsh[(rbase + lr + 8) * RGS2 + col] = make_float2(acc[bi][2], acc[bi][3]);
        }
        __syncthreads();

        // LSTM update: units 2j, 2j+1 at batch ub
        float gv[4][2];
#pragma unroll
        for (int g = 0; g < 4; g++) {
            gv[g][0] = xg[g][0] + gsh[(g * 32 + 2 * j) * RGS2 + ub];
            gv[g][1] = xg[g][1] + gsh[(g * 32 + 2 * j + 1) * RGS2 + ub];
        }
        cr0 = sigm(gv[1][0]) * cr0 + sigm(gv[0][0]) * tanhf(gv[2][0]);
        cr1 = sigm(gv[1][1]) * cr1 + sigm(gv[0][1]) * tanhf(gv[2][1]);
        float h0 = sigm(gv[3][0]) * tanhf(cr0);
        float h1 = sigm(gv[3][1]) * tanhf(cr1);

        // packed hi/lo store for next-step consumers
        uint32_t hiw = packbf2(h0, h1);
        __nv_bfloat162 hb = *(__nv_bfloat162*)&hiw;
        uint32_t low = packbf2(h0 - __low2float(hb), h1 - __high2float(hb));
        size_t kidx = ((size_t)t * NDIR + dir) * (128 * 256) +
                      (size_t)(u0 / 2 + j) * 256 + b0 + ub;
        hhi[kidx] = hiw;
        hlo[kidx] = low;

        // f32 store: L0 always (h0c feeds GEMMs); L1 only t=511 (FC head)
        if (NDIR == 2 || t == 511) {
            size_t orow = (size_t)t * HOUT_ROWS + dir * 256 + u0 + 2 * j;
            hout[orow * 256 + b0 + ub]       = h0;
            hout[(orow + 1) * 256 + b0 + ub] = h1;
        }

        group_barrier(grp, NG);   // __syncthreads + group release/acquire
    }
}

// ---------------------------------------------------------------------------
__global__ void finalize_kernel(const float* __restrict__ xp1r,
                                const float* __restrict__ h1last,
                                const float* __restrict__ fc_w,
                                const float* __restrict__ fc_b,
                                float* __restrict__ out) {
    int b = blockIdx.x, u = threadIdx.x;
    float ig = xp1r[(size_t)(0   + u) * 256 + b];
    float gg = xp1r[(size_t)(512 + u) * 256 + b];
    float og = xp1r[(size_t)(768 + u) * 256 + b];
    float cc = sigm(ig) * tanhf(gg);
    float hr = sigm(og) * tanhf(cc);
    float p = fc_w[u] * h1last[(size_t)u * 256 + b] + fc_w[256 + u] * hr;
    __shared__ float red[256];
    red[u] = p;
    __syncthreads();
    for (int off = 128; off > 0; off >>= 1) {
        if (u < off) red[u] += red[u + off];
        __syncthreads();
    }
    if (u == 0) out[b] = red[0] + fc_b[0];
}

// ---------------------------------------------------------------------------
extern "C" void kernel_launch(void* const* d_in, const int* in_sizes, int n_in,
                              void* d_out, int out_size) {
    const float* x        = (const float*)d_in[0];
    const float* w_ih_l0  = (const float*)d_in[1];
    const float* w_hh_l0  = (const float*)d_in[2];
    const float* b_ih_l0  = (const float*)d_in[3];
    const float* b_hh_l0  = (const float*)d_in[4];
    const float* w_ih_l0r = (const float*)d_in[5];
    const float* w_hh_l0r = (const float*)d_in[6];
    const float* b_ih_l0r = (const float*)d_in[7];
    const float* b_hh_l0r = (const float*)d_in[8];
    const float* w_ih_l1  = (const float*)d_in[9];
    const float* w_hh_l1  = (const float*)d_in[10];
    const float* b_ih_l1  = (const float*)d_in[11];
    const float* b_hh_l1  = (const float*)d_in[12];
    const float* w_ih_l1r = (const float*)d_in[13];
    const float* b_ih_l1r = (const float*)d_in[15];
    const float* b_hh_l1r = (const float*)d_in[16];
    const float* fc_w     = (const float*)d_in[17];
    const float* fc_b     = (const float*)d_in[18];
    float* out = (float*)d_out;
    (void)in_sizes; (void)n_in; (void)out_size;

    float *xT, *xp0f, *xp0r, *h0c, *xp1f, *xp1r, *h1;
    uint32_t *hhi, *hlo;
    cudaGetSymbolAddress((void**)&xT,   g_xT);
    cudaGetSymbolAddress((void**)&xp0f, g_xp0f);
    cudaGetSymbolAddress((void**)&xp0r, g_xp0r);
    cudaGetSymbolAddress((void**)&h0c,  g_h0c);
    cudaGetSymbolAddress((void**)&xp1f, g_xp1f);
    cudaGetSymbolAddress((void**)&xp1r, g_xp1r);
    cudaGetSymbolAddress((void**)&h1,   g_h1);
    cudaGetSymbolAddress((void**)&hhi,  g_hhi);
    cudaGetSymbolAddress((void**)&hlo,  g_hlo);

    const int REC_SMEM = (128 * WS2 * 2 + 128 * HS2B * 2 + 128 * RGS2) * 4;  // 194560
    cudaFuncSetAttribute((const void*)lstm_rec_mma<2>,
                         cudaFuncAttributeMaxDynamicSharedMemorySize, REC_SMEM);
    cudaFuncSetAttribute((const void*)lstm_rec_mma<1>,
                         cudaFuncAttributeMaxDynamicSharedMemorySize, REC_SMEM);

    transpose_x<<<dim3(1024, 8), dim3(32, 8)>>>(x, xT);
    gemm_tf32<<<dim3(512, 2, 8), 256>>>(xT, w_ih_l0,  b_ih_l0,  b_hh_l0,  xp0f, 64, 1024);
    gemm_tf32<<<dim3(512, 2, 8), 256>>>(xT, w_ih_l0r, b_ih_l0r, b_hh_l0r, xp0r, 64, 1024);
    lstm_rec_mma<2><<<128, 512, REC_SMEM>>>(xp0f, xp0r, w_hh_l0, w_hh_l0r, h0c, hhi, hlo);
    gemm_tf32<<<dim3(512, 2, 8), 256>>>(h0c, w_ih_l1, b_ih_l1, b_hh_l1, xp1f, 512, 1024);
    gemm_tf32<<<dim3(1, 2, 8), 256>>>(h0c + (size_t)511 * 512 * 256,
                                      w_ih_l1r, b_ih_l1r, b_hh_l1r, xp1r, 512, 1024);
    lstm_rec_mma<1><<<64, 512, REC_SMEM>>>(xp1f, xp1f, w_hh_l1, w_hh_l1, h1, hhi, hlo);
    finalize_kernel<<<256, 256>>>(xp1r, h1 + (size_t)511 * 256 * 256, fc_w, fc_b, out);
}

// round 11
// speedup vs baseline: 1.6762x; 1.0913x over previous
#include <cuda_runtime.h>
#include <cuda_bf16.h>
#include <cstdint>

// ---------------------------------------------------------------------------
// B=256, T=512, I=64, H=256, 2-layer bidirectional LSTM, FC on last timestep.
// R11: (1) flag-based group sync with per-launch base snapshots (replaces
//      serialized atomic chain; fixes R9's step-0 collision), (2) GEMM smem
//      double-buffering (one sync per k-iter). Rest identical to R10.
// ---------------------------------------------------------------------------

__device__ float    g_xT  [512 * 64 * 256];
__device__ float    g_xp0f[512 * 1024 * 256];
__device__ float    g_xp0r[512 * 1024 * 256];
__device__ float    g_h0c [512 * 512 * 256];
__device__ float    g_xp1f[512 * 1024 * 256];
__device__ float    g_xp1r[1024 * 256];
__device__ float    g_h1  [512 * 256 * 256];
__device__ uint32_t g_hhi [512 * 2 * 128 * 256];   // h packed bf16x2 hi [t*NDIR+dir][kp][b]
__device__ uint32_t g_hlo [512 * 2 * 128 * 256];   // h packed bf16x2 lo

__device__ unsigned g_gcnt [32 * 32];
__device__ unsigned g_ggen [32 * 32];
__device__ unsigned g_flags[16 * 32];              // [group][member], 128B-strided groups

__device__ __forceinline__ float sigm(float x) { return 1.0f / (1.0f + __expf(-x)); }

__device__ __forceinline__ uint32_t f2tf32(float x) {
    uint32_t r;
    asm("cvt.rna.tf32.f32 %0, %1;" : "=r"(r) : "f"(x));
    return r;
}

__device__ __forceinline__ void mma_tf32(float c[4], const uint32_t a[4], const uint32_t b[2]) {
    asm volatile(
        "mma.sync.aligned.m16n8k8.row.col.f32.tf32.tf32.f32 "
        "{%0,%1,%2,%3}, {%4,%5,%6,%7}, {%8,%9}, {%0,%1,%2,%3};"
        : "+f"(c[0]), "+f"(c[1]), "+f"(c[2]), "+f"(c[3])
        : "r"(a[0]), "r"(a[1]), "r"(a[2]), "r"(a[3]), "r"(b[0]), "r"(b[1]));
}

__device__ __forceinline__ void mma_bf16(float c[4], const uint32_t a[4], const uint32_t b[2]) {
    asm volatile(
        "mma.sync.aligned.m16n8k16.row.col.f32.bf16.bf16.f32 "
        "{%0,%1,%2,%3}, {%4,%5,%6,%7}, {%8,%9}, {%0,%1,%2,%3};"
        : "+f"(c[0]), "+f"(c[1]), "+f"(c[2]), "+f"(c[3])
        : "r"(a[0]), "r"(a[1]), "r"(a[2]), "r"(a[3]), "r"(b[0]), "r"(b[1]));
}

__device__ __forceinline__ uint32_t packbf2(float a, float b) {
    __nv_bfloat162 t = __floats2bfloat162_rn(a, b);
    return *(uint32_t*)&t;
}

// Proven acquire/release atomic group barrier (R8) — used ONCE per launch.
__device__ __forceinline__ void group_barrier_atomic(int grp, unsigned members) {
    __syncthreads();
    if (threadIdx.x == 0) {
        unsigned* cnt = &g_gcnt[grp * 32];
        unsigned* gen = &g_ggen[grp * 32];
        unsigned g0;
        asm volatile("ld.acquire.gpu.u32 %0, [%1];" : "=r"(g0) : "l"(gen));
        unsigned old;
        asm volatile("atom.acq_rel.gpu.add.u32 %0, [%1], 1;" : "=r"(old) : "l"(cnt));
        if (old == members - 1) {
            asm volatile("st.relaxed.gpu.u32 [%0], %1;" :: "l"(cnt), "r"(0u));
            asm volatile("red.release.gpu.add.u32 [%0], %1;" :: "l"(gen), "r"(1u));
        } else {
            unsigned g1;
            do {
                asm volatile("ld.acquire.gpu.u32 %0, [%1];" : "=r"(g1) : "l"(gen));
            } while (g1 == g0);
        }
    }
    __syncthreads();
}

// ---------------------------------------------------------------------------
__global__ void transpose_x(const float* __restrict__ x, float* __restrict__ xT) {
    __shared__ float tile[32][33];
    int c0 = blockIdx.x * 32, r0 = blockIdx.y * 32;
    int tx = threadIdx.x, ty = threadIdx.y;
#pragma unroll
    for (int i = 0; i < 32; i += 8)
        tile[ty + i][tx] = x[(size_t)(r0 + ty + i) * 32768 + c0 + tx];
    __syncthreads();
#pragma unroll
    for (int i = 0; i < 32; i += 8)
        xT[(size_t)(c0 + ty + i) * 256 + r0 + tx] = tile[tx][ty + i];
}

// ---------------------------------------------------------------------------
// TF32 tensor-core GEMM: register prefetch + smem double buffer (1 sync/iter).
// C[t][n][m] = sum_k W[n][k]*A[t][k][m] + b1[n] + b2[n]
// ---------------------------------------------------------------------------
#define WS_STRIDE 20
#define AS_STRIDE 132

__global__ void gemm_tf32(const float* __restrict__ A, const float* __restrict__ W,
                          const float* __restrict__ b1, const float* __restrict__ b2,
                          float* __restrict__ C, int K, int N) {
    __shared__ uint32_t Ws[2][128 * WS_STRIDE];
    __shared__ uint32_t As[2][16 * AS_STRIDE];

    int t  = blockIdx.x;
    int m0 = blockIdx.y * 128, n0 = blockIdx.z * 128;
    const float* At = A + (size_t)t * K * 256 + m0;
    const float* Wt = W + (size_t)n0 * K;
    float* Ct = C + (size_t)t * N * 256;

    int tid = threadIdx.x;
    int warp = tid >> 5, lane = tid & 31;
    int wn = (warp >> 2) * 64;
    int wb = (warp & 3) * 32;
    int lr = lane >> 2, lc = lane & 3;

    int a_kk = tid >> 5, a_b4 = (tid & 31) * 4;
    int w_n  = tid >> 2, w_kq = (tid & 3) * 4;

    float acc[4][4][4];
#pragma unroll
    for (int i = 0; i < 4; i++)
#pragma unroll
        for (int jj = 0; jj < 4; jj++)
#pragma unroll
            for (int r = 0; r < 4; r++) acc[i][jj][r] = 0.0f;

    float4 ra0, ra1, rw0, rw1;
    auto ld = [&](int k0) {
        ra0 = *(const float4*)&At[(size_t)(k0 + a_kk) * 256 + a_b4];
        ra1 = *(const float4*)&At[(size_t)(k0 + a_kk + 8) * 256 + a_b4];
        rw0 = *(const float4*)&Wt[(size_t)w_n * K + k0 + w_kq];
        rw1 = *(const float4*)&Wt[(size_t)(w_n + 64) * K + k0 + w_kq];
    };
    auto st = [&](int buf) {
        *(uint4*)&As[buf][a_kk * AS_STRIDE + a_b4] =
            make_uint4(f2tf32(ra0.x), f2tf32(ra0.y), f2tf32(ra0.z), f2tf32(ra0.w));
        *(uint4*)&As[buf][(a_kk + 8) * AS_STRIDE + a_b4] =
            make_uint4(f2tf32(ra1.x), f2tf32(ra1.y), f2tf32(ra1.z), f2tf32(ra1.w));
        *(uint4*)&Ws[buf][w_n * WS_STRIDE + w_kq] =
            make_uint4(f2tf32(rw0.x), f2tf32(rw0.y), f2tf32(rw0.z), f2tf32(rw0.w));
        *(uint4*)&Ws[buf][(w_n + 64) * WS_STRIDE + w_kq] =
            make_uint4(f2tf32(rw1.x), f2tf32(rw1.y), f2tf32(rw1.z), f2tf32(rw1.w));
    };

    int niter = K / 16;
    ld(0);
    st(0);
    __syncthreads();

    for (int it = 0; it < niter; it++) {
        int buf = it & 1;
        if (it + 1 < niter) ld((it + 1) * 16);   // LDG overlaps MMA below

#pragma unroll
        for (int ks = 0; ks < 2; ks++) {
            int kk = ks * 8;
            uint32_t a[4][4], b[4][2];
#pragma unroll
            for (int ni = 0; ni < 4; ni++) {
                int n = wn + ni * 16 + lr;
                a[ni][0] = Ws[buf][n * WS_STRIDE + kk + lc];
                a[ni][1] = Ws[buf][(n + 8) * WS_STRIDE + kk + lc];
                a[ni][2] = Ws[buf][n * WS_STRIDE + kk + lc + 4];
                a[ni][3] = Ws[buf][(n + 8) * WS_STRIDE + kk + lc + 4];
            }
#pragma unroll
            for (int bi = 0; bi < 4; bi++) {
                int bb = wb + bi * 8 + lr;
                b[bi][0] = As[buf][(kk + lc) * AS_STRIDE + bb];
                b[bi][1] = As[buf][(kk + lc + 4) * AS_STRIDE + bb];
            }
#pragma unroll
            for (int ni = 0; ni < 4; ni++)
#pragma unroll
                for (int bi = 0; bi < 4; bi++)
                    mma_tf32(acc[ni][bi], a[ni], b[bi]);
        }

        if (it + 1 < niter) {
            st(buf ^ 1);        // write other buffer (consumed 2 iters ago)
            __syncthreads();    // single sync per iteration
        }
    }

#pragma unroll
    for (int ni = 0; ni < 4; ni++) {
#pragma unroll
        for (int h = 0; h < 2; h++) {
            int n = n0 + wn + ni * 16 + lr + h * 8;
            float bias = b1[n] + b2[n];
#pragma unroll
            for (int bi = 0; bi < 4; bi++) {
                int bb = m0 + wb + bi * 8 + lc * 2;
                float2 v = make_float2(acc[ni][bi][h * 2] + bias,
                                       acc[ni][bi][h * 2 + 1] + bias);
                *(float2*)&Ct[(size_t)n * 256 + bb] = v;
            }
        }
    }
}

// ---------------------------------------------------------------------------
// bf16 tensor-core persistent recurrence, 512 threads/CTA.
// CTA = (dir, 32 units -> 128 gate rows, 32-batch slice); 8-member groups.
// Per-step sync: producer st.release(base+s+1); consumers poll (v-base)>=s.
// ---------------------------------------------------------------------------
#define WS2  132   // W2 row stride (128 kp + pad), mod32=4
#define HS2B 40    // H2 row stride (32 b + pad),  mod32=8
#define RGS2 36    // gsh row stride (32 b + pad)

template <int NDIR>
__global__ void __launch_bounds__(512, 1)
lstm_rec_mma(const float* __restrict__ xp_f, const float* __restrict__ xp_r,
             const float* __restrict__ whh_f, const float* __restrict__ whh_r,
             float* __restrict__ hout,
             uint32_t* __restrict__ hhi, uint32_t* __restrict__ hlo) {
    constexpr int NG = 8, BGN = 8;
    constexpr int HOUT_ROWS = NDIR * 256;

    extern __shared__ char smraw[];
    uint32_t* W2hi = (uint32_t*)smraw;                 // [128][132]
    uint32_t* W2lo = W2hi + 128 * WS2;
    uint32_t* H2hi = W2lo + 128 * WS2;                 // [128][40]
    uint32_t* H2lo = H2hi + 128 * HS2B;
    float*    gsh  = (float*)(H2lo + 128 * HS2B);      // [128][36]

    int tid = threadIdx.x;
    int bx  = blockIdx.x;
    int dir = (NDIR == 2) ? (bx / (NG * BGN)) : 0;
    int rem = bx % (NG * BGN);
    int ng = rem / BGN, bg = rem % BGN;
    int u0 = ng * 32, b0 = bg * 32;
    int grp = dir * BGN + bg;

    const float* xp  = dir ? xp_r : xp_f;
    const float* whh = dir ? whh_r : whh_f;

    // stage W_hh slice once: local row r = gate*32 + unit, k packed in pairs
    for (int i = tid; i < 128 * 128; i += 512) {
        int r = i >> 7, kp = i & 127;
        int grow = (r >> 5) * 256 + u0 + (r & 31);
        float2 w = *(const float2*)&whh[(size_t)grow * 256 + 2 * kp];
        uint32_t hi = packbf2(w.x, w.y);
        __nv_bfloat162 hb = *(__nv_bfloat162*)&hi;
        W2hi[r * WS2 + kp] = hi;
        W2lo[r * WS2 + kp] = packbf2(w.x - __low2float(hb), w.y - __high2float(hb));
    }

    int warp = tid >> 5, lane = tid & 31;
    int rbase = (warp & 7) * 16;        // 8 gate-row tiles (128 rows)
    int bbase = (warp >> 3) * 16;       // 2 batch tiles (32 b)
    int lr = lane >> 2, lc = lane & 3;

    // update mapping: unit pair j (0..15), batch ub (0..31)
    int j  = tid >> 5;
    int ub = tid & 31;
    float cr0 = 0.f, cr1 = 0.f;

    // flag bases: warp-0 lane i snapshots member i; tid 0 snapshots own flag.
    unsigned* myflag = &g_flags[grp * 32 + ng];
    unsigned memb_base = 0, my_base = 0;
    if (warp == 0 && lane < NG) {
        asm volatile("ld.relaxed.gpu.u32 %0, [%1];"
                     : "=r"(memb_base) : "l"(&g_flags[grp * 32 + lane]));
    }
    if (tid == 0) {
        asm volatile("ld.relaxed.gpu.u32 %0, [%1];" : "=r"(my_base) : "l"(myflag));
    }
    group_barrier_atomic(grp, NG);   // snapshots done before any new store

    for (int s = 0; s < 512; s++) {
        int t = dir ? (511 - s) : s;

        // prefetch xp gates for (units u0+2j, u0+2j+1, batch b0+ub)
        const float* xpt = xp + (size_t)t * 1024 * 256;
        float xg[4][2];
#pragma unroll
        for (int g = 0; g < 4; g++) {
            xg[g][0] = xpt[(size_t)(g * 256 + u0 + 2 * j) * 256 + b0 + ub];
            xg[g][1] = xpt[(size_t)(g * 256 + u0 + 2 * j + 1) * 256 + b0 + ub];
        }

        float acc[2][4];
#pragma unroll
        for (int bi = 0; bi < 2; bi++)
#pragma unroll
            for (int r = 0; r < 4; r++) acc[bi][r] = 0.0f;

        if (s > 0) {
            // wait: all members finished step s-1 (flag >= base + s)
            if (warp == 0 && lane < NG) {
                unsigned v;
                unsigned* fp = &g_flags[grp * 32 + lane];
                do {
                    asm volatile("ld.acquire.gpu.u32 %0, [%1];" : "=r"(v) : "l"(fp));
                } while ((v - memb_base) < (unsigned)s);
            }
            __syncthreads();

            int tp = dir ? (t + 1) : (t - 1);
            size_t hbase = ((size_t)tp * NDIR + dir) * (128 * 256);
            // stage h_prev (pure copy): 128 kp rows x 32 b words, hi+lo
#pragma unroll
            for (int q = 0; q < 2; q++) {
                int i = tid + 512 * q;
                int kp = i >> 3, qq = (i & 7) * 4;
                *(uint4*)&H2hi[kp * HS2B + qq] =
                    *(const uint4*)&hhi[hbase + (size_t)kp * 256 + b0 + qq];
                *(uint4*)&H2lo[kp * HS2B + qq] =
                    *(const uint4*)&hlo[hbase + (size_t)kp * 256 + b0 + qq];
            }
            __syncthreads();

#pragma unroll 4
            for (int ch = 0; ch < 16; ch++) {
                int kk2 = ch * 8;
                uint32_t ahi[4], alo[4];
                int ra = (rbase + lr) * WS2 + kk2 + lc;
                ahi[0] = W2hi[ra];            ahi[2] = W2hi[ra + 4];
                ahi[1] = W2hi[ra + 8 * WS2];  ahi[3] = W2hi[ra + 8 * WS2 + 4];
                alo[0] = W2lo[ra];            alo[2] = W2lo[ra + 4];
                alo[1] = W2lo[ra + 8 * WS2];  alo[3] = W2lo[ra + 8 * WS2 + 4];
#pragma unroll
                for (int bi = 0; bi < 2; bi++) {
                    int bcol = bbase + bi * 8 + lr;
                    uint32_t bhi[2], blo[2];
                    bhi[0] = H2hi[(kk2 + lc) * HS2B + bcol];
                    bhi[1] = H2hi[(kk2 + lc + 4) * HS2B + bcol];
                    blo[0] = H2lo[(kk2 + lc) * HS2B + bcol];
                    blo[1] = H2lo[(kk2 + lc + 4) * HS2B + bcol];
                    mma_bf16(acc[bi], ahi, bhi);
                    mma_bf16(acc[bi], ahi, blo);
                    mma_bf16(acc[bi], alo, bhi);
                }
            }
        }

        // gates -> gsh
#pragma unroll
        for (int bi = 0; bi < 2; bi++) {
            int col = bbase + bi * 8 + lc * 2;
            *(float2*)&gsh[(rbase + lr) * RGS2 + col]     = make_float2(acc[bi][0], acc[bi][1]);
            *(float2*)&gsh[(rbase + lr + 8) * RGS2 + col] = make_float2(acc[bi][2], acc[bi][3]);
        }
        __syncthreads();

        // LSTM update: units 2j, 2j+1 at batch ub
        float gv[4][2];
#pragma unroll
        for (int g = 0; g < 4; g++) {
            gv[g][0] = xg[g][0] + gsh[(g * 32 + 2 * j) * RGS2 + ub];
            gv[g][1] = xg[g][1] + gsh[(g * 32 + 2 * j + 1) * RGS2 + ub];
        }
        cr0 = sigm(gv[1][0]) * cr0 + sigm(gv[0][0]) * tanhf(gv[2][0]);
        cr1 = sigm(gv[1][1]) * cr1 + sigm(gv[0][1]) * tanhf(gv[2][1]);
        float h0 = sigm(gv[3][0]) * tanhf(cr0);
        float h1 = sigm(gv[3][1]) * tanhf(cr1);

        // packed hi/lo store for next-step consumers
        uint32_t hiw = packbf2(h0, h1);
        __nv_bfloat162 hb = *(__nv_bfloat162*)&hiw;
        uint32_t low = packbf2(h0 - __low2float(hb), h1 - __high2float(hb));
        size_t kidx = ((size_t)t * NDIR + dir) * (128 * 256) +
                      (size_t)(u0 / 2 + j) * 256 + b0 + ub;
        hhi[kidx] = hiw;
        hlo[kidx] = low;

        // f32 store: L0 always (h0c feeds GEMMs); L1 only t=511 (FC head)
        if (NDIR == 2 || t == 511) {
            size_t orow = (size_t)t * HOUT_ROWS + dir * 256 + u0 + 2 * j;
            hout[orow * 256 + b0 + ub]       = h0;
            hout[(orow + 1) * 256 + b0 + ub] = h1;
        }

        __syncthreads();   // all h stores done CTA-wide before release
        if (tid == 0) {
            asm volatile("st.release.gpu.u32 [%0], %1;"
                         :: "l"(myflag), "r"(my_base + (unsigned)s + 1u));
        }
    }
}

// ---------------------------------------------------------------------------
__global__ void finalize_kernel(const float* __restrict__ xp1r,
                                const float* __restrict__ h1last,
                                const float* __restrict__ fc_w,
                                const float* __restrict__ fc_b,
                                float* __restrict__ out) {
    int b = blockIdx.x, u = threadIdx.x;
    float ig = xp1r[(size_t)(0   + u) * 256 + b];
    float gg = xp1r[(size_t)(512 + u) * 256 + b];
    float og = xp1r[(size_t)(768 + u) * 256 + b];
    float cc = sigm(ig) * tanhf(gg);
    float hr = sigm(og) * tanhf(cc);
    float p = fc_w[u] * h1last[(size_t)u * 256 + b] + fc_w[256 + u] * hr;
    __shared__ float red[256];
    red[u] = p;
    __syncthreads();
    for (int off = 128; off > 0; off >>= 1) {
        if (u < off) red[u] += red[u + off];
        __syncthreads();
    }
    if (u == 0) out[b] = red[0] + fc_b[0];
}

// ---------------------------------------------------------------------------
extern "C" void kernel_launch(void* const* d_in, const int* in_sizes, int n_in,
                              void* d_out, int out_size) {
    const float* x        = (const float*)d_in[0];
    const float* w_ih_l0  = (const float*)d_in[1];
    const float* w_hh_l0  = (const float*)d_in[2];
    const float* b_ih_l0  = (const float*)d_in[3];
    const float* b_hh_l0  = (const float*)d_in[4];
    const float* w_ih_l0r = (const float*)d_in[5];
    const float* w_hh_l0r = (const float*)d_in[6];
    const float* b_ih_l0r = (const float*)d_in[7];
    const float* b_hh_l0r = (const float*)d_in[8];
    const float* w_ih_l1  = (const float*)d_in[9];
    const float* w_hh_l1  = (const float*)d_in[10];
    const float* b_ih_l1  = (const float*)d_in[11];
    const float* b_hh_l1  = (const float*)d_in[12];
    const float* w_ih_l1r = (const float*)d_in[13];
    const float* b_ih_l1r = (const float*)d_in[15];
    const float* b_hh_l1r = (const float*)d_in[16];
    const float* fc_w     = (const float*)d_in[17];
    const float* fc_b     = (const float*)d_in[18];
    float* out = (float*)d_out;
    (void)in_sizes; (void)n_in; (void)out_size;

    float *xT, *xp0f, *xp0r, *h0c, *xp1f, *xp1r, *h1;
    uint32_t *hhi, *hlo;
    cudaGetSymbolAddress((void**)&xT,   g_xT);
    cudaGetSymbolAddress((void**)&xp0f, g_xp0f);
    cudaGetSymbolAddress((void**)&xp0r, g_xp0r);
    cudaGetSymbolAddress((void**)&h0c,  g_h0c);
    cudaGetSymbolAddress((void**)&xp1f, g_xp1f);
    cudaGetSymbolAddress((void**)&xp1r, g_xp1r);
    cudaGetSymbolAddress((void**)&h1,   g_h1);
    cudaGetSymbolAddress((void**)&hhi,  g_hhi);
    cudaGetSymbolAddress((void**)&hlo,  g_hlo);

    const int REC_SMEM = (128 * WS2 * 2 + 128 * HS2B * 2 + 128 * RGS2) * 4;  // 194560
    cudaFuncSetAttribute((const void*)lstm_rec_mma<2>,
                         cudaFuncAttributeMaxDynamicSharedMemorySize, REC_SMEM);
    cudaFuncSetAttribute((const void*)lstm_rec_mma<1>,
                         cudaFuncAttributeMaxDynamicSharedMemorySize, REC_SMEM);

    transpose_x<<<dim3(1024, 8), dim3(32, 8)>>>(x, xT);
    gemm_tf32<<<dim3(512, 2, 8), 256>>>(xT, w_ih_l0,  b_ih_l0,  b_hh_l0,  xp0f, 64, 1024);
    gemm_tf32<<<dim3(512, 2, 8), 256>>>(xT, w_ih_l0r, b_ih_l0r, b_hh_l0r, xp0r, 64, 1024);
    lstm_rec_mma<2><<<128, 512, REC_SMEM>>>(xp0f, xp0r, w_hh_l0, w_hh_l0r, h0c, hhi, hlo);
    gemm_tf32<<<dim3(512, 2, 8), 256>>>(h0c, w_ih_l1, b_ih_l1, b_hh_l1, xp1f, 512, 1024);
    gemm_tf32<<<dim3(1, 2, 8), 256>>>(h0c + (size_t)511 * 512 * 256,
                                      w_ih_l1r, b_ih_l1r, b_hh_l1r, xp1r, 512, 1024);
    lstm_rec_mma<1><<<64, 512, REC_SMEM>>>(xp1f, xp1f, w_hh_l1, w_hh_l1, h1, hhi, hlo);
    finalize_kernel<<<256, 256>>>(xp1r, h1 + (size_t)511 * 256 * 256, fc_w, fc_b, out);
}

// round 12
// speedup vs baseline: 1.7296x; 1.0319x over previous
#include <cuda_runtime.h>
#include <cuda_bf16.h>
#include <cstdint>

// ---------------------------------------------------------------------------
// B=256, T=512, I=64, H=256, 2-layer bidirectional LSTM, FC on last timestep.
// R12: GEMM inputs pre-rounded to tf32 (bit-exact vs staging-time cvt.rna,
//      proven R7) + 3-stage cp.async pipeline (pure copies, no CVTs, ~600cyc
//      LDG latency hidden). Recurrence unchanged except h0c stores rounded.
// ---------------------------------------------------------------------------

__device__ float    g_xT  [512 * 64 * 256];
__device__ float    g_xp0f[512 * 1024 * 256];
__device__ float    g_xp0r[512 * 1024 * 256];
__device__ float    g_h0c [512 * 512 * 256];
__device__ float    g_xp1f[512 * 1024 * 256];
__device__ float    g_xp1r[1024 * 256];
__device__ float    g_h1  [512 * 256 * 256];
__device__ uint32_t g_hhi [512 * 2 * 128 * 256];   // h packed bf16x2 hi
__device__ uint32_t g_hlo [512 * 2 * 128 * 256];   // h packed bf16x2 lo
__device__ float    g_wt  [1024 * (64 + 64 + 512 + 512)];  // tf32-rounded W_ih's

__device__ unsigned g_gcnt [32 * 32];
__device__ unsigned g_ggen [32 * 32];
__device__ unsigned g_flags[16 * 32];

__device__ __forceinline__ float sigm(float x) { return 1.0f / (1.0f + __expf(-x)); }

__device__ __forceinline__ uint32_t f2tf32(float x) {
    uint32_t r;
    asm("cvt.rna.tf32.f32 %0, %1;" : "=r"(r) : "f"(x));
    return r;
}

__device__ __forceinline__ void mma_tf32(float c[4], const uint32_t a[4], const uint32_t b[2]) {
    asm volatile(
        "mma.sync.aligned.m16n8k8.row.col.f32.tf32.tf32.f32 "
        "{%0,%1,%2,%3}, {%4,%5,%6,%7}, {%8,%9}, {%0,%1,%2,%3};"
        : "+f"(c[0]), "+f"(c[1]), "+f"(c[2]), "+f"(c[3])
        : "r"(a[0]), "r"(a[1]), "r"(a[2]), "r"(a[3]), "r"(b[0]), "r"(b[1]));
}

__device__ __forceinline__ void mma_bf16(float c[4], const uint32_t a[4], const uint32_t b[2]) {
    asm volatile(
        "mma.sync.aligned.m16n8k16.row.col.f32.bf16.bf16.f32 "
        "{%0,%1,%2,%3}, {%4,%5,%6,%7}, {%8,%9}, {%0,%1,%2,%3};"
        : "+f"(c[0]), "+f"(c[1]), "+f"(c[2]), "+f"(c[3])
        : "r"(a[0]), "r"(a[1]), "r"(a[2]), "r"(a[3]), "r"(b[0]), "r"(b[1]));
}

__device__ __forceinline__ uint32_t packbf2(float a, float b) {
    __nv_bfloat162 t = __floats2bfloat162_rn(a, b);
    return *(uint32_t*)&t;
}

__device__ __forceinline__ void cp_async16(void* smem_dst, const void* gptr) {
    uint32_t sa = (uint32_t)__cvta_generic_to_shared(smem_dst);
    asm volatile("cp.async.cg.shared.global [%0], [%1], 16;" :: "r"(sa), "l"(gptr));
}
__device__ __forceinline__ void cp_commit() { asm volatile("cp.async.commit_group;"); }
template <int N>
__device__ __forceinline__ void cp_wait() { asm volatile("cp.async.wait_group %0;" :: "n"(N)); }

// Proven acquire/release atomic group barrier — used ONCE per launch.
__device__ __forceinline__ void group_barrier_atomic(int grp, unsigned members) {
    __syncthreads();
    if (threadIdx.x == 0) {
        unsigned* cnt = &g_gcnt[grp * 32];
        unsigned* gen = &g_ggen[grp * 32];
        unsigned g0;
        asm volatile("ld.acquire.gpu.u32 %0, [%1];" : "=r"(g0) : "l"(gen));
        unsigned old;
        asm volatile("atom.acq_rel.gpu.add.u32 %0, [%1], 1;" : "=r"(old) : "l"(cnt));
        if (old == members - 1) {
            asm volatile("st.relaxed.gpu.u32 [%0], %1;" :: "l"(cnt), "r"(0u));
            asm volatile("red.release.gpu.add.u32 [%0], %1;" :: "l"(gen), "r"(1u));
        } else {
            unsigned g1;
            do {
                asm volatile("ld.acquire.gpu.u32 %0, [%1];" : "=r"(g1) : "l"(gen));
            } while (g1 == g0);
        }
    }
    __syncthreads();
}

// ---------------------------------------------------------------------------
// Transpose + tf32-round: x[b][t*64+k] -> xT[(t*64+k)][b]
// ---------------------------------------------------------------------------
__global__ void transpose_x(const float* __restrict__ x, float* __restrict__ xT) {
    __shared__ float tile[32][33];
    int c0 = blockIdx.x * 32, r0 = blockIdx.y * 32;
    int tx = threadIdx.x, ty = threadIdx.y;
#pragma unroll
    for (int i = 0; i < 32; i += 8)
        tile[ty + i][tx] = x[(size_t)(r0 + ty + i) * 32768 + c0 + tx];
    __syncthreads();
#pragma unroll
    for (int i = 0; i < 32; i += 8)
        xT[(size_t)(c0 + ty + i) * 256 + r0 + tx] =
            __uint_as_float(f2tf32(tile[tx][ty + i]));
}

// tf32-round a buffer (weight pre-conversion)
__global__ void cvt_tf32(const float* __restrict__ in, float* __restrict__ out, int n) {
    int i = blockIdx.x * 256 + threadIdx.x;
    if (i < n) out[i] = __uint_as_float(f2tf32(in[i]));
}

// ---------------------------------------------------------------------------
// TF32 GEMM: pre-rounded inputs, 3-stage cp.async pipeline, 1 sync/iter.
// C[t][n][m] = sum_k W[n][k]*A[t][k][m] + b1[n] + b2[n]
// ---------------------------------------------------------------------------
#define WS_STRIDE 20
#define AS_STRIDE 132
#define GEMM_SMEM ((3 * 128 * WS_STRIDE + 3 * 16 * AS_STRIDE) * 4)   // 56064 B

__global__ void gemm_tf32(const float* __restrict__ A, const float* __restrict__ W,
                          const float* __restrict__ b1, const float* __restrict__ b2,
                          float* __restrict__ C, int K, int N) {
    extern __shared__ uint32_t gsm[];
    uint32_t* WsBase = gsm;                              // [3][128*20]
    uint32_t* AsBase = gsm + 3 * 128 * WS_STRIDE;        // [3][16*132]

    int t  = blockIdx.x;
    int m0 = blockIdx.y * 128, n0 = blockIdx.z * 128;
    const float* At = A + (size_t)t * K * 256 + m0;
    const float* Wt = W + (size_t)n0 * K;
    float* Ct = C + (size_t)t * N * 256;

    int tid = threadIdx.x;
    int warp = tid >> 5, lane = tid & 31;
    int wn = (warp >> 2) * 64;
    int wb = (warp & 3) * 32;
    int lr = lane >> 2, lc = lane & 3;

    // staging maps (traced: full coverage, 16B-aligned)
    int a_kk = tid >> 5, a_b4 = (tid & 31) * 4;   // A rows a_kk, a_kk+8; 16B chunks
    int w_n  = tid >> 1, w_k8 = (tid & 1) * 8;    // W row w_n, floats [w_k8, w_k8+8)

    float acc[4][4][4];
#pragma unroll
    for (int i = 0; i < 4; i++)
#pragma unroll
        for (int jj = 0; jj < 4; jj++)
#pragma unroll
            for (int r = 0; r < 4; r++) acc[i][jj][r] = 0.0f;

    auto stage = [&](int buf, int k0) {
        uint32_t* Asb = AsBase + buf * 16 * AS_STRIDE;
        uint32_t* Wsb = WsBase + buf * 128 * WS_STRIDE;
        cp_async16(&Asb[a_kk * AS_STRIDE + a_b4],
                   &At[(size_t)(k0 + a_kk) * 256 + a_b4]);
        cp_async16(&Asb[(a_kk + 8) * AS_STRIDE + a_b4],
                   &At[(size_t)(k0 + a_kk + 8) * 256 + a_b4]);
        cp_async16(&Wsb[w_n * WS_STRIDE + w_k8],
                   &Wt[(size_t)w_n * K + k0 + w_k8]);
        cp_async16(&Wsb[w_n * WS_STRIDE + w_k8 + 4],
                   &Wt[(size_t)w_n * K + k0 + w_k8 + 4]);
    };

    int niter = K / 16;
    stage(0, 0);
    cp_commit();
    if (niter > 1) { stage(1, 16); cp_commit(); }

    for (int it = 0; it < niter; it++) {
        int buf = it % 3;
        if (it + 1 < niter) cp_wait<1>(); else cp_wait<0>();
        __syncthreads();

        uint32_t* Asb = AsBase + buf * 16 * AS_STRIDE;
        uint32_t* Wsb = WsBase + buf * 128 * WS_STRIDE;
#pragma unroll
        for (int ks = 0; ks < 2; ks++) {
            int kk = ks * 8;
            uint32_t a[4][4], b[4][2];
#pragma unroll
            for (int ni = 0; ni < 4; ni++) {
                int n = wn + ni * 16 + lr;
                a[ni][0] = Wsb[n * WS_STRIDE + kk + lc];
                a[ni][1] = Wsb[(n + 8) * WS_STRIDE + kk + lc];
                a[ni][2] = Wsb[n * WS_STRIDE + kk + lc + 4];
                a[ni][3] = Wsb[(n + 8) * WS_STRIDE + kk + lc + 4];
            }
#pragma unroll
            for (int bi = 0; bi < 4; bi++) {
                int bb = wb + bi * 8 + lr;
                b[bi][0] = Asb[(kk + lc) * AS_STRIDE + bb];
                b[bi][1] = Asb[(kk + lc + 4) * AS_STRIDE + bb];
            }
#pragma unroll
            for (int ni = 0; ni < 4; ni++)
#pragma unroll
                for (int bi = 0; bi < 4; bi++)
                    mma_tf32(acc[ni][bi], a[ni], b[bi]);
        }

        if (it + 2 < niter) {
            stage((it + 2) % 3, (it + 2) * 16);
            cp_commit();
        }
    }

#pragma unroll
    for (int ni = 0; ni < 4; ni++) {
#pragma unroll
        for (int h = 0; h < 2; h++) {
            int n = n0 + wn + ni * 16 + lr + h * 8;
            float bias = b1[n] + b2[n];
#pragma unroll
            for (int bi = 0; bi < 4; bi++) {
                int bb = m0 + wb + bi * 8 + lc * 2;
                float2 v = make_float2(acc[ni][bi][h * 2] + bias,
                                       acc[ni][bi][h * 2 + 1] + bias);
                *(float2*)&Ct[(size_t)n * 256 + bb] = v;
            }
        }
    }
}

// ---------------------------------------------------------------------------
// bf16 tensor-core persistent recurrence (unchanged from R11 except
// h0c f32 stores are tf32-rounded for the downstream GEMM).
// ---------------------------------------------------------------------------
#define WS2  132
#define HS2B 40
#define RGS2 36

template <int NDIR>
__global__ void __launch_bounds__(512, 1)
lstm_rec_mma(const float* __restrict__ xp_f, const float* __restrict__ xp_r,
             const float* __restrict__ whh_f, const float* __restrict__ whh_r,
             float* __restrict__ hout,
             uint32_t* __restrict__ hhi, uint32_t* __restrict__ hlo) {
    constexpr int NG = 8, BGN = 8;
    constexpr int HOUT_ROWS = NDIR * 256;

    extern __shared__ char smraw[];
    uint32_t* W2hi = (uint32_t*)smraw;
    uint32_t* W2lo = W2hi + 128 * WS2;
    uint32_t* H2hi = W2lo + 128 * WS2;
    uint32_t* H2lo = H2hi + 128 * HS2B;
    float*    gsh  = (float*)(H2lo + 128 * HS2B);

    int tid = threadIdx.x;
    int bx  = blockIdx.x;
    int dir = (NDIR == 2) ? (bx / (NG * BGN)) : 0;
    int rem = bx % (NG * BGN);
    int ng = rem / BGN, bg = rem % BGN;
    int u0 = ng * 32, b0 = bg * 32;
    int grp = dir * BGN + bg;

    const float* xp  = dir ? xp_r : xp_f;
    const float* whh = dir ? whh_r : whh_f;

    for (int i = tid; i < 128 * 128; i += 512) {
        int r = i >> 7, kp = i & 127;
        int grow = (r >> 5) * 256 + u0 + (r & 31);
        float2 w = *(const float2*)&whh[(size_t)grow * 256 + 2 * kp];
        uint32_t hi = packbf2(w.x, w.y);
        __nv_bfloat162 hb = *(__nv_bfloat162*)&hi;
        W2hi[r * WS2 + kp] = hi;
        W2lo[r * WS2 + kp] = packbf2(w.x - __low2float(hb), w.y - __high2float(hb));
    }

    int warp = tid >> 5, lane = tid & 31;
    int rbase = (warp & 7) * 16;
    int bbase = (warp >> 3) * 16;
    int lr = lane >> 2, lc = lane & 3;

    int j  = tid >> 5;
    int ub = tid & 31;
    float cr0 = 0.f, cr1 = 0.f;

    unsigned* myflag = &g_flags[grp * 32 + ng];
    unsigned memb_base = 0, my_base = 0;
    if (warp == 0 && lane < NG) {
        asm volatile("ld.relaxed.gpu.u32 %0, [%1];"
                     : "=r"(memb_base) : "l"(&g_flags[grp * 32 + lane]));
    }
    if (tid == 0) {
        asm volatile("ld.relaxed.gpu.u32 %0, [%1];" : "=r"(my_base) : "l"(myflag));
    }
    group_barrier_atomic(grp, NG);

    for (int s = 0; s < 512; s++) {
        int t = dir ? (511 - s) : s;

        const float* xpt = xp + (size_t)t * 1024 * 256;
        float xg[4][2];
#pragma unroll
        for (int g = 0; g < 4; g++) {
            xg[g][0] = xpt[(size_t)(g * 256 + u0 + 2 * j) * 256 + b0 + ub];
            xg[g][1] = xpt[(size_t)(g * 256 + u0 + 2 * j + 1) * 256 + b0 + ub];
        }

        float acc[2][4];
#pragma unroll
        for (int bi = 0; bi < 2; bi++)
#pragma unroll
            for (int r = 0; r < 4; r++) acc[bi][r] = 0.0f;

        if (s > 0) {
            if (warp == 0 && lane < NG) {
                unsigned v;
                unsigned* fp = &g_flags[grp * 32 + lane];
                do {
                    asm volatile("ld.acquire.gpu.u32 %0, [%1];" : "=r"(v) : "l"(fp));
                } while ((v - memb_base) < (unsigned)s);
            }
            __syncthreads();

            int tp = dir ? (t + 1) : (t - 1);
            size_t hbase = ((size_t)tp * NDIR + dir) * (128 * 256);
#pragma unroll
            for (int q = 0; q < 2; q++) {
                int i = tid + 512 * q;
                int kp = i >> 3, qq = (i & 7) * 4;
                *(uint4*)&H2hi[kp * HS2B + qq] =
                    *(const uint4*)&hhi[hbase + (size_t)kp * 256 + b0 + qq];
                *(uint4*)&H2lo[kp * HS2B + qq] =
                    *(const uint4*)&hlo[hbase + (size_t)kp * 256 + b0 + qq];
            }
            __syncthreads();

#pragma unroll 4
            for (int ch = 0; ch < 16; ch++) {
                int kk2 = ch * 8;
                uint32_t ahi[4], alo[4];
                int ra = (rbase + lr) * WS2 + kk2 + lc;
                ahi[0] = W2hi[ra];            ahi[2] = W2hi[ra + 4];
                ahi[1] = W2hi[ra + 8 * WS2];  ahi[3] = W2hi[ra + 8 * WS2 + 4];
                alo[0] = W2lo[ra];            alo[2] = W2lo[ra + 4];
                alo[1] = W2lo[ra + 8 * WS2];  alo[3] = W2lo[ra + 8 * WS2 + 4];
#pragma unroll
                for (int bi = 0; bi < 2; bi++) {
                    int bcol = bbase + bi * 8 + lr;
                    uint32_t bhi[2], blo[2];
                    bhi[0] = H2hi[(kk2 + lc) * HS2B + bcol];
                    bhi[1] = H2hi[(kk2 + lc + 4) * HS2B + bcol];
                    blo[0] = H2lo[(kk2 + lc) * HS2B + bcol];
                    blo[1] = H2lo[(kk2 + lc + 4) * HS2B + bcol];
                    mma_bf16(acc[bi], ahi, bhi);
                    mma_bf16(acc[bi], ahi, blo);
                    mma_bf16(acc[bi], alo, bhi);
                }
            }
        }

#pragma unroll
        for (int bi = 0; bi < 2; bi++) {
            int col = bbase + bi * 8 + lc * 2;
            *(float2*)&gsh[(rbase + lr) * RGS2 + col]     = make_float2(acc[bi][0], acc[bi][1]);
            *(float2*)&gsh[(rbase + lr + 8) * RGS2 + col] = make_float2(acc[bi][2], acc[bi][3]);
        }
        __syncthreads();

        float gv[4][2];
#pragma unroll
        for (int g = 0; g < 4; g++) {
            gv[g][0] = xg[g][0] + gsh[(g * 32 + 2 * j) * RGS2 + ub];
            gv[g][1] = xg[g][1] + gsh[(g * 32 + 2 * j + 1) * RGS2 + ub];
        }
        cr0 = sigm(gv[1][0]) * cr0 + sigm(gv[0][0]) * tanhf(gv[2][0]);
        cr1 = sigm(gv[1][1]) * cr1 + sigm(gv[0][1]) * tanhf(gv[2][1]);
        float h0 = sigm(gv[3][0]) * tanhf(cr0);
        float h1 = sigm(gv[3][1]) * tanhf(cr1);

        uint32_t hiw = packbf2(h0, h1);
        __nv_bfloat162 hb = *(__nv_bfloat162*)&hiw;
        uint32_t low = packbf2(h0 - __low2float(hb), h1 - __high2float(hb));
        size_t kidx = ((size_t)t * NDIR + dir) * (128 * 256) +
                      (size_t)(u0 / 2 + j) * 256 + b0 + ub;
        hhi[kidx] = hiw;
        hlo[kidx] = low;

        // f32 store: L0 rounds to tf32 (h0c only feeds tf32 GEMMs);
        //            L1 stores full f32 at t=511 only (FC head).
        if (NDIR == 2 || t == 511) {
            float o0 = (NDIR == 2) ? __uint_as_float(f2tf32(h0)) : h0;
            float o1 = (NDIR == 2) ? __uint_as_float(f2tf32(h1)) : h1;
            size_t orow = (size_t)t * HOUT_ROWS + dir * 256 + u0 + 2 * j;
            hout[orow * 256 + b0 + ub]       = o0;
            hout[(orow + 1) * 256 + b0 + ub] = o1;
        }

        __syncthreads();
        if (tid == 0) {
            asm volatile("st.release.gpu.u32 [%0], %1;"
                         :: "l"(myflag), "r"(my_base + (unsigned)s + 1u));
        }
    }
}

// ---------------------------------------------------------------------------
__global__ void finalize_kernel(const float* __restrict__ xp1r,
                                const float* __restrict__ h1last,
                                const float* __restrict__ fc_w,
                                const float* __restrict__ fc_b,
                                float* __restrict__ out) {
    int b = blockIdx.x, u = threadIdx.x;
    float ig = xp1r[(size_t)(0   + u) * 256 + b];
    float gg = xp1r[(size_t)(512 + u) * 256 + b];
    float og = xp1r[(size_t)(768 + u) * 256 + b];
    float cc = sigm(ig) * tanhf(gg);
    float hr = sigm(og) * tanhf(cc);
    float p = fc_w[u] * h1last[(size_t)u * 256 + b] + fc_w[256 + u] * hr;
    __shared__ float red[256];
    red[u] = p;
    __syncthreads();
    for (int off = 128; off > 0; off >>= 1) {
        if (u < off) red[u] += red[u + off];
        __syncthreads();
    }
    if (u == 0) out[b] = red[0] + fc_b[0];
}

// ---------------------------------------------------------------------------
extern "C" void kernel_launch(void* const* d_in, const int* in_sizes, int n_in,
                              void* d_out, int out_size) {
    const float* x        = (const float*)d_in[0];
    const float* w_ih_l0  = (const float*)d_in[1];
    const float* w_hh_l0  = (const float*)d_in[2];
    const float* b_ih_l0  = (const float*)d_in[3];
    const float* b_hh_l0  = (const float*)d_in[4];
    const float* w_ih_l0r = (const float*)d_in[5];
    const float* w_hh_l0r = (const float*)d_in[6];
    const float* b_ih_l0r = (const float*)d_in[7];
    const float* b_hh_l0r = (const float*)d_in[8];
    const float* w_ih_l1  = (const float*)d_in[9];
    const float* w_hh_l1  = (const float*)d_in[10];
    const float* b_ih_l1  = (const float*)d_in[11];
    const float* b_hh_l1  = (const float*)d_in[12];
    const float* w_ih_l1r = (const float*)d_in[13];
    const float* b_ih_l1r = (const float*)d_in[15];
    const float* b_hh_l1r = (const float*)d_in[16];
    const float* fc_w     = (const float*)d_in[17];
    const float* fc_b     = (const float*)d_in[18];
    float* out = (float*)d_out;
    (void)in_sizes; (void)n_in; (void)out_size;

    float *xT, *xp0f, *xp0r, *h0c, *xp1f, *xp1r, *h1, *wt;
    uint32_t *hhi, *hlo;
    cudaGetSymbolAddress((void**)&xT,   g_xT);
    cudaGetSymbolAddress((void**)&xp0f, g_xp0f);
    cudaGetSymbolAddress((void**)&xp0r, g_xp0r);
    cudaGetSymbolAddress((void**)&h0c,  g_h0c);
    cudaGetSymbolAddress((void**)&xp1f, g_xp1f);
    cudaGetSymbolAddress((void**)&xp1r, g_xp1r);
    cudaGetSymbolAddress((void**)&h1,   g_h1);
    cudaGetSymbolAddress((void**)&wt,   g_wt);
    cudaGetSymbolAddress((void**)&hhi,  g_hhi);
    cudaGetSymbolAddress((void**)&hlo,  g_hlo);

    float* wt_l0  = wt;
    float* wt_l0r = wt + 1024 * 64;
    float* wt_l1  = wt + 1024 * 128;
    float* wt_l1r = wt + 1024 * 128 + 1024 * 512;

    const int REC_SMEM = (128 * WS2 * 2 + 128 * HS2B * 2 + 128 * RGS2) * 4;  // 194560
    cudaFuncSetAttribute((const void*)lstm_rec_mma<2>,
                         cudaFuncAttributeMaxDynamicSharedMemorySize, REC_SMEM);
    cudaFuncSetAttribute((const void*)lstm_rec_mma<1>,
                         cudaFuncAttributeMaxDynamicSharedMemorySize, REC_SMEM);
    cudaFuncSetAttribute((const void*)gemm_tf32,
                         cudaFuncAttributeMaxDynamicSharedMemorySize, GEMM_SMEM);

    // weight pre-conversion (tiny)
    cvt_tf32<<<(1024 * 64  + 255) / 256, 256>>>(w_ih_l0,  wt_l0,  1024 * 64);
    cvt_tf32<<<(1024 * 64  + 255) / 256, 256>>>(w_ih_l0r, wt_l0r, 1024 * 64);
    cvt_tf32<<<(1024 * 512 + 255) / 256, 256>>>(w_ih_l1,  wt_l1,  1024 * 512);
    cvt_tf32<<<(1024 * 512 + 255) / 256, 256>>>(w_ih_l1r, wt_l1r, 1024 * 512);

    transpose_x<<<dim3(1024, 8), dim3(32, 8)>>>(x, xT);
    gemm_tf32<<<dim3(512, 2, 8), 256, GEMM_SMEM>>>(xT, wt_l0,  b_ih_l0,  b_hh_l0,  xp0f, 64, 1024);
    gemm_tf32<<<dim3(512, 2, 8), 256, GEMM_SMEM>>>(xT, wt_l0r, b_ih_l0r, b_hh_l0r, xp0r, 64, 1024);
    lstm_rec_mma<2><<<128, 512, REC_SMEM>>>(xp0f, xp0r, w_hh_l0, w_hh_l0r, h0c, hhi, hlo);
    gemm_tf32<<<dim3(512, 2, 8), 256, GEMM_SMEM>>>(h0c, wt_l1, b_ih_l1, b_hh_l1, xp1f, 512, 1024);
    gemm_tf32<<<dim3(1, 2, 8), 256, GEMM_SMEM>>>(h0c + (size_t)511 * 512 * 256,
                                                 wt_l1r, b_ih_l1r, b_hh_l1r, xp1r, 512, 1024);
    lstm_rec_mma<1><<<64, 512, REC_SMEM>>>(xp1f, xp1f, w_hh_l1, w_hh_l1, h1, hhi, hlo);
    finalize_kernel<<<256, 256>>>(xp1r, h1 + (size_t)511 * 256 * 256, fc_w, fc_b, out);
}